// round 1
// baseline (speedup 1.0000x reference)
#include <cuda_runtime.h>
#include <cuda_bf16.h>
#include <math_constants.h>

// Problem dims
#define BB   2048
#define II   4096
#define DD   512
#define IE_  512
#define UE_  1024
#define D1_  1024
#define D2_  512
#define D3_  256

// ---------------- scratch (alloc-free rule: __device__ globals) ----------------
__device__ float g_rs   [II];
__device__ float g_w    [(size_t)BB * II];
__device__ float g_uf   [(size_t)BB * DD];
__device__ float g_ih1  [(size_t)BB * (2*IE_)];
__device__ float g_uh1  [(size_t)BB * (2*UE_)];
__device__ float g_xcat [(size_t)BB * (IE_ + UE_)];
__device__ float g_x1   [(size_t)BB * D1_];
__device__ float g_x2   [(size_t)BB * D2_];
__device__ float g_x3   [(size_t)BB * D3_];

// ---------------- rs[i] = rated_items[i,:] . att_w[D:2D] ----------------
__global__ void rs_kernel(const float* __restrict__ rated,
                          const float* __restrict__ attw,
                          float* __restrict__ rs) {
    int row  = blockIdx.x * 8 + (threadIdx.x >> 5);
    int lane = threadIdx.x & 31;
    const float* r  = rated + (size_t)row * DD;
    const float* wr = attw + DD;
    float s = 0.f;
    #pragma unroll 4
    for (int k = lane; k < DD; k += 32) s += r[k] * wr[k];
    #pragma unroll
    for (int o = 16; o > 0; o >>= 1) s += __shfl_xor_sync(0xffffffffu, s, o);
    if (lane == 0) rs[row] = s;
}

// ---------------- w[b,i] = um[b,i] * softmax_masked(rs)[i] ----------------
// Row-constant terms (cand@wc, att_b) cancel in softmax, so only rs matters.
// All-masked row -> Z=0 -> invz=0 -> row of zeros (matches nan_to_num).
__global__ void attw_kernel(const float* __restrict__ um,
                            const float* __restrict__ rs,
                            float* __restrict__ w) {
    const int b = blockIdx.x;
    const float* umr = um + (size_t)b * II;
    float*       wr  = w  + (size_t)b * II;
    __shared__ float red[256];
    const int tid = threadIdx.x;

    float m = -CUDART_INF_F;
    for (int i = tid; i < II; i += 256) {
        float u = umr[i];
        if (u != 0.0f) m = fmaxf(m, rs[i]);
    }
    red[tid] = m; __syncthreads();
    for (int s = 128; s > 0; s >>= 1) {
        if (tid < s) red[tid] = fmaxf(red[tid], red[tid + s]);
        __syncthreads();
    }
    m = red[0];
    __syncthreads();

    float z = 0.f;
    for (int i = tid; i < II; i += 256) {
        float u = umr[i];
        if (u != 0.0f) z += __expf(rs[i] - m);
    }
    red[tid] = z; __syncthreads();
    for (int s = 128; s > 0; s >>= 1) {
        if (tid < s) red[tid] += red[tid + s];
        __syncthreads();
    }
    z = red[0];
    const float invz = (z > 0.f) ? (1.f / z) : 0.f;

    for (int i = tid; i < II; i += 256) {
        float u = umr[i];
        wr[i] = (u != 0.0f) ? u * __expf(rs[i] - m) * invz : 0.0f;
    }
}

// ---------------- tiled SGEMM: C = [relu](A @ W [+ bias]) ----------------
// A: MxK row-major, W: KxN row-major, C row stride ldc.
// BM=BN=64, BK=16, 256 threads, 4x4 register tile. All dims multiples of tiles.
template <bool RELU, bool HAS_BIAS>
__global__ void gemm_bias(const float* __restrict__ A,
                          const float* __restrict__ W,
                          const float* __restrict__ bias,
                          float* __restrict__ C,
                          int M, int N, int K, int ldc) {
    const int lda = K, ldw = N;
    const int tid = threadIdx.x;
    const int tr  = tid >> 4;
    const int tc  = tid & 15;
    const int rowBase = blockIdx.y * 64;
    const int colBase = blockIdx.x * 64;

    __shared__ float As[16][64];
    __shared__ float Bs[16][64];

    const int ar = tid >> 2;
    const int ak = (tid & 3) * 4;
    const int bk = tid >> 4;
    const int bc = (tid & 15) * 4;

    float acc[4][4];
    #pragma unroll
    for (int i = 0; i < 4; ++i)
        #pragma unroll
        for (int j = 0; j < 4; ++j) acc[i][j] = 0.f;

    for (int k0 = 0; k0 < K; k0 += 16) {
        float4 av = *(const float4*)(A + (size_t)(rowBase + ar) * lda + k0 + ak);
        As[ak + 0][ar] = av.x; As[ak + 1][ar] = av.y;
        As[ak + 2][ar] = av.z; As[ak + 3][ar] = av.w;
        *(float4*)&Bs[bk][bc] =
            *(const float4*)(W + (size_t)(k0 + bk) * ldw + colBase + bc);
        __syncthreads();

        #pragma unroll
        for (int k = 0; k < 16; ++k) {
            float4 a4 = *(const float4*)&As[k][tr * 4];
            float4 b4 = *(const float4*)&Bs[k][tc * 4];
            float a[4] = {a4.x, a4.y, a4.z, a4.w};
            float b[4] = {b4.x, b4.y, b4.z, b4.w};
            #pragma unroll
            for (int i = 0; i < 4; ++i)
                #pragma unroll
                for (int j = 0; j < 4; ++j)
                    acc[i][j] = fmaf(a[i], b[j], acc[i][j]);
        }
        __syncthreads();
    }

    const int col0 = colBase + tc * 4;
    float bb[4] = {0.f, 0.f, 0.f, 0.f};
    if (HAS_BIAS) {
        float4 bv = *(const float4*)(bias + col0);
        bb[0] = bv.x; bb[1] = bv.y; bb[2] = bv.z; bb[3] = bv.w;
    }
    #pragma unroll
    for (int i = 0; i < 4; ++i) {
        const int row = rowBase + tr * 4 + i;
        float v[4];
        #pragma unroll
        for (int j = 0; j < 4; ++j) {
            v[j] = acc[i][j] + bb[j];
            if (RELU) v[j] = fmaxf(v[j], 0.f);
        }
        float4 o = {v[0], v[1], v[2], v[3]};
        *(float4*)(C + (size_t)row * ldc + col0) = o;
    }
}

// ---------------- out[b] = x3[b,:] . mw4 + mb4 ----------------
__global__ void final_kernel(const float* __restrict__ x3,
                             const float* __restrict__ mw4,
                             const float* __restrict__ mb4,
                             float* __restrict__ out) {
    int row  = blockIdx.x * 8 + (threadIdx.x >> 5);
    int lane = threadIdx.x & 31;
    const float* x = x3 + (size_t)row * D3_;
    float s = 0.f;
    #pragma unroll
    for (int k = lane; k < D3_; k += 32) s += x[k] * mw4[k];
    #pragma unroll
    for (int o = 16; o > 0; o >>= 1) s += __shfl_xor_sync(0xffffffffu, s, o);
    if (lane == 0) out[row] = s + mb4[0];
}

// ---------------- launch ----------------
extern "C" void kernel_launch(void* const* d_in, const int* in_sizes, int n_in,
                              void* d_out, int out_size) {
    const float* cand  = (const float*)d_in[0];
    const float* rated = (const float*)d_in[1];
    const float* um    = (const float*)d_in[2];
    const float* attw  = (const float*)d_in[3];
    // d_in[4] = att_b: cancels in the masked softmax, unused.
    const float* iw1 = (const float*)d_in[5];
    const float* ib1 = (const float*)d_in[6];
    const float* iw2 = (const float*)d_in[7];
    const float* ib2 = (const float*)d_in[8];
    const float* uw1 = (const float*)d_in[9];
    const float* ub1 = (const float*)d_in[10];
    const float* uw2 = (const float*)d_in[11];
    const float* ub2 = (const float*)d_in[12];
    const float* mw1 = (const float*)d_in[13];
    const float* mb1 = (const float*)d_in[14];
    const float* mw2 = (const float*)d_in[15];
    const float* mb2 = (const float*)d_in[16];
    const float* mw3 = (const float*)d_in[17];
    const float* mb3 = (const float*)d_in[18];
    const float* mw4 = (const float*)d_in[19];
    const float* mb4 = (const float*)d_in[20];
    float* out = (float*)d_out;

    float *rs, *w, *uf, *ih1, *uh1, *xcat, *x1, *x2, *x3;
    cudaGetSymbolAddress((void**)&rs,   g_rs);
    cudaGetSymbolAddress((void**)&w,    g_w);
    cudaGetSymbolAddress((void**)&uf,   g_uf);
    cudaGetSymbolAddress((void**)&ih1,  g_ih1);
    cudaGetSymbolAddress((void**)&uh1,  g_uh1);
    cudaGetSymbolAddress((void**)&xcat, g_xcat);
    cudaGetSymbolAddress((void**)&x1,   g_x1);
    cudaGetSymbolAddress((void**)&x2,   g_x2);
    cudaGetSymbolAddress((void**)&x3,   g_x3);

    rs_kernel<<<II / 8, 256>>>(rated, attw, rs);
    attw_kernel<<<BB, 256>>>(um, rs, w);

    { dim3 g(DD / 64, BB / 64);           // user_feat = w @ rated  (no bias)
      gemm_bias<false, false><<<g, 256>>>(w, rated, nullptr, uf, BB, DD, II, DD); }
    { dim3 g((2 * IE_) / 64, BB / 64);    // ih1 = relu(cand @ iw1 + ib1)
      gemm_bias<true, true><<<g, 256>>>(cand, iw1, ib1, ih1, BB, 2 * IE_, DD, 2 * IE_); }
    { dim3 g(IE_ / 64, BB / 64);          // item_emb -> xcat[:, :512]
      gemm_bias<true, true><<<g, 256>>>(ih1, iw2, ib2, xcat, BB, IE_, 2 * IE_, IE_ + UE_); }
    { dim3 g((2 * UE_) / 64, BB / 64);    // uh1 = relu(uf @ uw1 + ub1)
      gemm_bias<true, true><<<g, 256>>>(uf, uw1, ub1, uh1, BB, 2 * UE_, DD, 2 * UE_); }
    { dim3 g(UE_ / 64, BB / 64);          // user_emb -> xcat[:, 512:]
      gemm_bias<true, true><<<g, 256>>>(uh1, uw2, ub2, xcat + IE_, BB, UE_, 2 * UE_, IE_ + UE_); }
    { dim3 g(D1_ / 64, BB / 64);          // x1 = relu(xcat @ mw1 + mb1)
      gemm_bias<true, true><<<g, 256>>>(xcat, mw1, mb1, x1, BB, D1_, IE_ + UE_, D1_); }
    { dim3 g(D2_ / 64, BB / 64);          // x2 = relu(x1 @ mw2 + mb2)
      gemm_bias<true, true><<<g, 256>>>(x1, mw2, mb2, x2, BB, D2_, D1_, D2_); }
    { dim3 g(D3_ / 64, BB / 64);          // x3 = relu(x2 @ mw3 + mb3)
      gemm_bias<true, true><<<g, 256>>>(x2, mw3, mb3, x3, BB, D3_, D2_, D3_); }

    final_kernel<<<BB / 8, 256>>>(x3, mw4, mb4, out);
}

// round 2
// speedup vs baseline: 1.4416x; 1.4416x over previous
#include <cuda_runtime.h>
#include <cuda_bf16.h>
#include <math_constants.h>

// Problem dims
#define BB   2048
#define II   4096
#define DD   512
#define IE_  512
#define UE_  1024
#define D1_  1024
#define D2_  512
#define D3_  256

// ---------------- scratch (alloc-free rule: __device__ globals) ----------------
__device__ float g_rs   [II];
__device__ float g_w    [(size_t)BB * II];
__device__ float g_uf   [(size_t)BB * DD];
__device__ float g_ih1  [(size_t)BB * (2*IE_)];
__device__ float g_uh1  [(size_t)BB * (2*UE_)];
__device__ float g_xcat [(size_t)BB * (IE_ + UE_)];
__device__ float g_x1   [(size_t)BB * D1_];
__device__ float g_x2   [(size_t)BB * D2_];
__device__ float g_x3   [(size_t)BB * D3_];
__device__ float g_part [(size_t)4 * BB * DD];   // split-K partials (max 4 x 2048 x 512)

// ---------------- rs[i] = rated_items[i,:] . att_w[D:2D] ----------------
__global__ void rs_kernel(const float* __restrict__ rated,
                          const float* __restrict__ attw,
                          float* __restrict__ rs) {
    int row  = blockIdx.x * 8 + (threadIdx.x >> 5);
    int lane = threadIdx.x & 31;
    const float* r  = rated + (size_t)row * DD;
    const float* wr = attw + DD;
    float s = 0.f;
    #pragma unroll 4
    for (int k = lane; k < DD; k += 32) s += r[k] * wr[k];
    #pragma unroll
    for (int o = 16; o > 0; o >>= 1) s += __shfl_xor_sync(0xffffffffu, s, o);
    if (lane == 0) rs[row] = s;
}

// ---------------- w[b,i] = um[b,i] * softmax_masked(rs)[i] ----------------
// Row-constant terms (cand@wc, att_b) cancel in softmax. All-masked row ->
// Z=0 -> invz=0 -> zero row (matches nan_to_num).
__global__ void attw_kernel(const float* __restrict__ um,
                            const float* __restrict__ rs,
                            float* __restrict__ w) {
    const int b = blockIdx.x;
    const float* umr = um + (size_t)b * II;
    float*       wr  = w  + (size_t)b * II;
    __shared__ float red[256];
    const int tid = threadIdx.x;

    float m = -CUDART_INF_F;
    for (int i = tid; i < II; i += 256) {
        float u = umr[i];
        if (u != 0.0f) m = fmaxf(m, rs[i]);
    }
    red[tid] = m; __syncthreads();
    for (int s = 128; s > 0; s >>= 1) {
        if (tid < s) red[tid] = fmaxf(red[tid], red[tid + s]);
        __syncthreads();
    }
    m = red[0];
    __syncthreads();

    float z = 0.f;
    for (int i = tid; i < II; i += 256) {
        float u = umr[i];
        if (u != 0.0f) z += __expf(rs[i] - m);
    }
    red[tid] = z; __syncthreads();
    for (int s = 128; s > 0; s >>= 1) {
        if (tid < s) red[tid] += red[tid + s];
        __syncthreads();
    }
    z = red[0];
    const float invz = (z > 0.f) ? (1.f / z) : 0.f;

    for (int i = tid; i < II; i += 256) {
        float u = umr[i];
        wr[i] = (u != 0.0f) ? u * __expf(rs[i] - m) * invz : 0.0f;
    }
}

// ---------------- 128x128x8 double-buffered SGEMM, 8x8 microtile ----------------
// A: MxK row-major, W: KxN row-major. Unsplit: C=[relu](A@W[+bias]), row stride ldc.
// SPLITK: blockIdx.z selects K-chunk; writes raw partial to C + z*M*N (ld=N).
// All dims multiples of tiles; K chunk multiple of 8.
template <bool RELU, bool HAS_BIAS, bool SPLITK>
__global__ void __launch_bounds__(256, 2)
gemm128(const float* __restrict__ A,
        const float* __restrict__ W,
        const float* __restrict__ bias,
        float* __restrict__ C,
        int M, int N, int K, int ldc) {
    const int lda = K, ldw = N;
    int kBeg = 0, kLen = K;
    if (SPLITK) {
        kLen = K / gridDim.z;
        kBeg = blockIdx.z * kLen;
        C += (size_t)blockIdx.z * M * N;
        ldc = N;
    }

    __shared__ float As[2][8][128];
    __shared__ float Bs[2][8][128];

    const int tid = threadIdx.x;
    const int rowBase = blockIdx.y * 128;
    const int colBase = blockIdx.x * 128;

    const int arow = tid >> 1;           // 0..127
    const int acol = (tid & 1) * 4;      // 0 or 4
    const int brow = tid >> 5;           // 0..7
    const int bcol = (tid & 31) * 4;     // 0..124

    const float* Aptr = A + (size_t)(rowBase + arow) * lda + kBeg + acol;
    const float* Wptr = W + (size_t)(kBeg + brow) * ldw + colBase + bcol;

    const int tr = tid >> 4;             // 0..15
    const int tc = tid & 15;             // 0..15

    float acc[8][8];
    #pragma unroll
    for (int i = 0; i < 8; ++i)
        #pragma unroll
        for (int j = 0; j < 8; ++j) acc[i][j] = 0.f;

    // preload tile 0
    {
        float4 a0 = *(const float4*)Aptr;
        float4 b0 = *(const float4*)Wptr;
        As[0][acol + 0][arow] = a0.x;
        As[0][acol + 1][arow] = a0.y;
        As[0][acol + 2][arow] = a0.z;
        As[0][acol + 3][arow] = a0.w;
        *(float4*)&Bs[0][brow][bcol] = b0;
    }
    __syncthreads();

    const int nT = kLen >> 3;
    for (int t = 0; t < nT; ++t) {
        const int buf = t & 1;
        float4 aN, bN;
        const bool more = (t + 1 < nT);
        if (more) {
            aN = *(const float4*)(Aptr + (t + 1) * 8);
            bN = *(const float4*)(Wptr + (size_t)(t + 1) * 8 * ldw);
        }
        #pragma unroll
        for (int k = 0; k < 8; ++k) {
            float4 x0 = *(const float4*)&As[buf][k][tr * 4];
            float4 x1 = *(const float4*)&As[buf][k][tr * 4 + 64];
            float4 y0 = *(const float4*)&Bs[buf][k][tc * 4];
            float4 y1 = *(const float4*)&Bs[buf][k][tc * 4 + 64];
            float av[8] = {x0.x, x0.y, x0.z, x0.w, x1.x, x1.y, x1.z, x1.w};
            float bv[8] = {y0.x, y0.y, y0.z, y0.w, y1.x, y1.y, y1.z, y1.w};
            #pragma unroll
            for (int i = 0; i < 8; ++i)
                #pragma unroll
                for (int j = 0; j < 8; ++j)
                    acc[i][j] = fmaf(av[i], bv[j], acc[i][j]);
        }
        if (more) {
            const int nb = buf ^ 1;
            As[nb][acol + 0][arow] = aN.x;
            As[nb][acol + 1][arow] = aN.y;
            As[nb][acol + 2][arow] = aN.z;
            As[nb][acol + 3][arow] = aN.w;
            *(float4*)&Bs[nb][brow][bcol] = bN;
            __syncthreads();
        }
    }

    // epilogue
    float bb[8] = {0.f, 0.f, 0.f, 0.f, 0.f, 0.f, 0.f, 0.f};
    if (HAS_BIAS) {
        float4 v0 = *(const float4*)(bias + colBase + tc * 4);
        float4 v1 = *(const float4*)(bias + colBase + tc * 4 + 64);
        bb[0] = v0.x; bb[1] = v0.y; bb[2] = v0.z; bb[3] = v0.w;
        bb[4] = v1.x; bb[5] = v1.y; bb[6] = v1.z; bb[7] = v1.w;
    }
    #pragma unroll
    for (int i = 0; i < 8; ++i) {
        const int row = rowBase + tr * 4 + (i & 3) + ((i >> 2) * 64);
        float* cp = C + (size_t)row * ldc + colBase;
        float v[8];
        #pragma unroll
        for (int j = 0; j < 8; ++j) {
            v[j] = acc[i][j] + bb[j];
            if (RELU) v[j] = fmaxf(v[j], 0.f);
        }
        float4 o0 = {v[0], v[1], v[2], v[3]};
        float4 o1 = {v[4], v[5], v[6], v[7]};
        *(float4*)(cp + tc * 4)      = o0;
        *(float4*)(cp + tc * 4 + 64) = o1;
    }
}

// ---------------- split-K combine: C = [relu](sum_z part[z] [+ bias]) ----------------
template <bool RELU, bool HAS_BIAS, int S>
__global__ void combine_k(const float* __restrict__ part,
                          const float* __restrict__ bias,
                          float* __restrict__ C,
                          int M, int N, int ldc) {
    const int idx = blockIdx.x * blockDim.x + threadIdx.x;  // float4 index
    const int nq = N >> 2;
    if (idx >= M * nq) return;
    const int row = idx / nq;
    const int c0  = (idx - row * nq) * 4;
    const size_t off = (size_t)row * N + c0;
    float4 s = *(const float4*)(part + off);
    #pragma unroll
    for (int z = 1; z < S; ++z) {
        float4 p = *(const float4*)(part + (size_t)z * M * N + off);
        s.x += p.x; s.y += p.y; s.z += p.z; s.w += p.w;
    }
    if (HAS_BIAS) {
        float4 b = *(const float4*)(bias + c0);
        s.x += b.x; s.y += b.y; s.z += b.z; s.w += b.w;
    }
    if (RELU) {
        s.x = fmaxf(s.x, 0.f); s.y = fmaxf(s.y, 0.f);
        s.z = fmaxf(s.z, 0.f); s.w = fmaxf(s.w, 0.f);
    }
    *(float4*)(C + (size_t)row * ldc + c0) = s;
}

// ---------------- out[b] = x3[b,:] . mw4 + mb4 ----------------
__global__ void final_kernel(const float* __restrict__ x3,
                             const float* __restrict__ mw4,
                             const float* __restrict__ mb4,
                             float* __restrict__ out) {
    int row  = blockIdx.x * 8 + (threadIdx.x >> 5);
    int lane = threadIdx.x & 31;
    const float* x = x3 + (size_t)row * D3_;
    float s = 0.f;
    #pragma unroll
    for (int k = lane; k < D3_; k += 32) s += x[k] * mw4[k];
    #pragma unroll
    for (int o = 16; o > 0; o >>= 1) s += __shfl_xor_sync(0xffffffffu, s, o);
    if (lane == 0) out[row] = s + mb4[0];
}

// ---------------- launch ----------------
extern "C" void kernel_launch(void* const* d_in, const int* in_sizes, int n_in,
                              void* d_out, int out_size) {
    const float* cand  = (const float*)d_in[0];
    const float* rated = (const float*)d_in[1];
    const float* um    = (const float*)d_in[2];
    const float* attw  = (const float*)d_in[3];
    // d_in[4] = att_b: cancels in the masked softmax, unused.
    const float* iw1 = (const float*)d_in[5];
    const float* ib1 = (const float*)d_in[6];
    const float* iw2 = (const float*)d_in[7];
    const float* ib2 = (const float*)d_in[8];
    const float* uw1 = (const float*)d_in[9];
    const float* ub1 = (const float*)d_in[10];
    const float* uw2 = (const float*)d_in[11];
    const float* ub2 = (const float*)d_in[12];
    const float* mw1 = (const float*)d_in[13];
    const float* mb1 = (const float*)d_in[14];
    const float* mw2 = (const float*)d_in[15];
    const float* mb2 = (const float*)d_in[16];
    const float* mw3 = (const float*)d_in[17];
    const float* mb3 = (const float*)d_in[18];
    const float* mw4 = (const float*)d_in[19];
    const float* mb4 = (const float*)d_in[20];
    float* out = (float*)d_out;

    float *rs, *w, *uf, *ih1, *uh1, *xcat, *x1, *x2, *x3, *part;
    cudaGetSymbolAddress((void**)&rs,   g_rs);
    cudaGetSymbolAddress((void**)&w,    g_w);
    cudaGetSymbolAddress((void**)&uf,   g_uf);
    cudaGetSymbolAddress((void**)&ih1,  g_ih1);
    cudaGetSymbolAddress((void**)&uh1,  g_uh1);
    cudaGetSymbolAddress((void**)&xcat, g_xcat);
    cudaGetSymbolAddress((void**)&x1,   g_x1);
    cudaGetSymbolAddress((void**)&x2,   g_x2);
    cudaGetSymbolAddress((void**)&x3,   g_x3);
    cudaGetSymbolAddress((void**)&part, g_part);

    rs_kernel<<<II / 8, 256>>>(rated, attw, rs);
    attw_kernel<<<BB, 256>>>(um, rs, w);

    // uf = w @ rated  (2048 x 512 x 4096), split-K=4 -> 256 CTAs
    { dim3 g(DD / 128, BB / 128, 4);
      gemm128<false, false, true><<<g, 256>>>(w, rated, nullptr, part, BB, DD, II, DD);
      int n4 = BB * DD / 4;
      combine_k<false, false, 4><<<(n4 + 255) / 256, 256>>>(part, nullptr, uf, BB, DD, DD); }

    // ih1 = relu(cand @ iw1 + ib1)  (2048 x 1024 x 512), 128 CTAs
    { dim3 g((2 * IE_) / 128, BB / 128);
      gemm128<true, true, false><<<g, 256>>>(cand, iw1, ib1, ih1, BB, 2 * IE_, DD, 2 * IE_); }

    // item_emb = relu(ih1 @ iw2 + ib2) -> xcat[:, :512], split-K=2
    { dim3 g(IE_ / 128, BB / 128, 2);
      gemm128<false, false, true><<<g, 256>>>(ih1, iw2, nullptr, part, BB, IE_, 2 * IE_, IE_);
      int n4 = BB * IE_ / 4;
      combine_k<true, true, 2><<<(n4 + 255) / 256, 256>>>(part, ib2, xcat, BB, IE_, IE_ + UE_); }

    // uh1 = relu(uf @ uw1 + ub1)  (2048 x 2048 x 512), 256 CTAs
    { dim3 g((2 * UE_) / 128, BB / 128);
      gemm128<true, true, false><<<g, 256>>>(uf, uw1, ub1, uh1, BB, 2 * UE_, DD, 2 * UE_); }

    // user_emb = relu(uh1 @ uw2 + ub2) -> xcat[:, 512:], 128 CTAs
    { dim3 g(UE_ / 128, BB / 128);
      gemm128<true, true, false><<<g, 256>>>(uh1, uw2, ub2, xcat + IE_, BB, UE_, 2 * UE_, IE_ + UE_); }

    // x1 = relu(xcat @ mw1 + mb1)  (2048 x 1024 x 1536), 128 CTAs
    { dim3 g(D1_ / 128, BB / 128);
      gemm128<true, true, false><<<g, 256>>>(xcat, mw1, mb1, x1, BB, D1_, IE_ + UE_, D1_); }

    // x2 = relu(x1 @ mw2 + mb2)  (2048 x 512 x 1024), split-K=2
    { dim3 g(D2_ / 128, BB / 128, 2);
      gemm128<false, false, true><<<g, 256>>>(x1, mw2, nullptr, part, BB, D2_, D1_, D2_);
      int n4 = BB * D2_ / 4;
      combine_k<true, true, 2><<<(n4 + 255) / 256, 256>>>(part, mb2, x2, BB, D2_, D2_); }

    // x3 = relu(x2 @ mw3 + mb3)  (2048 x 256 x 512), split-K=4
    { dim3 g(D3_ / 128, BB / 128, 4);
      gemm128<false, false, true><<<g, 256>>>(x2, mw3, nullptr, part, BB, D3_, D2_, D3_);
      int n4 = BB * D3_ / 4;
      combine_k<true, true, 4><<<(n4 + 255) / 256, 256>>>(part, mb3, x3, BB, D3_, D3_); }

    final_kernel<<<BB / 8, 256>>>(x3, mw4, mb4, out);
}

// round 3
// speedup vs baseline: 2.6892x; 1.8654x over previous
#include <cuda_runtime.h>
#include <cuda_bf16.h>
#include <math_constants.h>
#include <cstdint>

// Problem dims
#define BB   2048
#define II   4096
#define DD   512
#define IE_  512
#define UE_  1024
#define D1_  1024
#define D2_  512
#define D3_  256

// ---------------- scratch (alloc-free rule: __device__ globals) ----------------
__device__ float g_rs   [II];
__device__ float g_w    [(size_t)BB * II];
__device__ float g_uf   [(size_t)BB * DD];
__device__ float g_ih1  [(size_t)BB * (2*IE_)];
__device__ float g_uh1  [(size_t)BB * (2*UE_)];
__device__ float g_xcat [(size_t)BB * (IE_ + UE_)];
__device__ float g_x1   [(size_t)BB * D1_];
__device__ float g_x2   [(size_t)BB * D2_];
__device__ float g_x3   [(size_t)BB * D3_];
__device__ float g_part [(size_t)4 * BB * DD];   // split-K partials

// ---------------- helpers ----------------
__device__ __forceinline__ float tf32r(float x) {
    float y;
    asm("cvt.rna.tf32.f32 %0, %1;" : "=f"(y) : "f"(x));
    return y;
}

__device__ __forceinline__ void mma_tf32(float* c, const uint32_t* a, const uint32_t* b) {
    asm volatile(
        "mma.sync.aligned.m16n8k8.row.col.f32.tf32.tf32.f32 "
        "{%0,%1,%2,%3}, {%4,%5,%6,%7}, {%8,%9}, {%0,%1,%2,%3};"
        : "+f"(c[0]), "+f"(c[1]), "+f"(c[2]), "+f"(c[3])
        : "r"(a[0]), "r"(a[1]), "r"(a[2]), "r"(a[3]), "r"(b[0]), "r"(b[1]));
}

// ---------------- rs[i] = rated_items[i,:] . att_w[D:2D] ----------------
__global__ void rs_kernel(const float* __restrict__ rated,
                          const float* __restrict__ attw,
                          float* __restrict__ rs) {
    int row  = blockIdx.x * 8 + (threadIdx.x >> 5);
    int lane = threadIdx.x & 31;
    const float* r  = rated + (size_t)row * DD;
    const float* wr = attw + DD;
    float s = 0.f;
    #pragma unroll 4
    for (int k = lane; k < DD; k += 32) s += r[k] * wr[k];
    #pragma unroll
    for (int o = 16; o > 0; o >>= 1) s += __shfl_xor_sync(0xffffffffu, s, o);
    if (lane == 0) rs[row] = s;
}

// ---------------- w[b,i] = um[b,i] * softmax_masked(rs)[i] ----------------
// Row-constant softmax terms cancel. um row cached in smem (one HBM read),
// exp cached in smem (computed once). All-masked row -> invz=0 -> zeros.
__global__ void attw_kernel(const float* __restrict__ um,
                            const float* __restrict__ rs,
                            float* __restrict__ w) {
    __shared__ float s_um[II];
    __shared__ float s_e[II];
    __shared__ float red[256];
    const int b = blockIdx.x;
    const float* umr = um + (size_t)b * II;
    float*       wr  = w  + (size_t)b * II;
    const int tid = threadIdx.x;

    for (int i = tid; i < II; i += 256) s_um[i] = umr[i];
    __syncthreads();

    float m = -CUDART_INF_F;
    for (int i = tid; i < II; i += 256)
        if (s_um[i] != 0.0f) m = fmaxf(m, rs[i]);
    red[tid] = m; __syncthreads();
    for (int s = 128; s > 0; s >>= 1) {
        if (tid < s) red[tid] = fmaxf(red[tid], red[tid + s]);
        __syncthreads();
    }
    m = red[0];
    __syncthreads();

    float z = 0.f;
    for (int i = tid; i < II; i += 256) {
        float e = (s_um[i] != 0.0f) ? __expf(rs[i] - m) : 0.0f;
        s_e[i] = e;
        z += e;
    }
    red[tid] = z; __syncthreads();
    for (int s = 128; s > 0; s >>= 1) {
        if (tid < s) red[tid] += red[tid + s];
        __syncthreads();
    }
    z = red[0];
    const float invz = (z > 0.f) ? (1.f / z) : 0.f;

    for (int i = tid; i < II; i += 256)
        wr[i] = s_um[i] * s_e[i] * invz;
}

// ---------------- TF32 tensor-core GEMM: 128x128x16 tiles ----------------
// A: MxK row-major, W: KxN row-major. 256 threads = 8 warps (2m x 4n),
// warp tile 64x32 built from m16n8k8 mma (4 m-tiles x 4 n-tiles).
// Unsplit: C = [relu](A@W [+bias]) with row stride ldc.
// SPLITK: blockIdx.z selects K-chunk, raw partial to C + z*M*N (ld = N).
// All dims multiples of tiles; K chunk multiple of 16.
template <bool RELU, bool HAS_BIAS, bool SPLITK>
__global__ void __launch_bounds__(256, 2)
gemm_tc(const float* __restrict__ A,
        const float* __restrict__ W,
        const float* __restrict__ bias,
        float* __restrict__ C,
        int M, int N, int K, int ldc) {
    const int lda = K, ldw = N;
    int kBeg = 0, kLen = K;
    if (SPLITK) {
        kLen = K / gridDim.z;
        kBeg = blockIdx.z * kLen;
        C += (size_t)blockIdx.z * M * N;
        ldc = N;
    }

    __shared__ float As[2][16][136];  // [k][m], padded: conflict-free frag loads
    __shared__ float Bs[2][16][136];  // [k][n]

    const int tid  = threadIdx.x;
    const int warp = tid >> 5;
    const int lane = tid & 31;
    const int g    = lane >> 2;      // group id 0..7
    const int tg   = lane & 3;       // thread-in-group 0..3
    const int wm   = warp >> 2;      // 0..1
    const int wn   = warp & 3;       // 0..3
    const int rowBase = blockIdx.y * 128;
    const int colBase = blockIdx.x * 128;

    // loaders
    const int arow = tid >> 1;           // 0..127
    const int acol = (tid & 1) * 8;      // 0 or 8
    const int brow = tid >> 4;           // 0..15
    const int bcol = (tid & 15) * 8;     // 0..120

    const float* Ap = A + (size_t)(rowBase + arow) * lda + kBeg + acol;
    const float* Wp = W + (size_t)(kBeg + brow) * ldw + colBase + bcol;

    float acc[4][4][4];
    #pragma unroll
    for (int mt = 0; mt < 4; ++mt)
        #pragma unroll
        for (int nt = 0; nt < 4; ++nt)
            #pragma unroll
            for (int r = 0; r < 4; ++r) acc[mt][nt][r] = 0.f;

    // preload tile 0
    {
        float4 a0 = *(const float4*)Ap;
        float4 a1 = *(const float4*)(Ap + 4);
        float4 b0 = *(const float4*)Wp;
        float4 b1 = *(const float4*)(Wp + 4);
        As[0][acol + 0][arow] = tf32r(a0.x);
        As[0][acol + 1][arow] = tf32r(a0.y);
        As[0][acol + 2][arow] = tf32r(a0.z);
        As[0][acol + 3][arow] = tf32r(a0.w);
        As[0][acol + 4][arow] = tf32r(a1.x);
        As[0][acol + 5][arow] = tf32r(a1.y);
        As[0][acol + 6][arow] = tf32r(a1.z);
        As[0][acol + 7][arow] = tf32r(a1.w);
        float4 c0 = {tf32r(b0.x), tf32r(b0.y), tf32r(b0.z), tf32r(b0.w)};
        float4 c1 = {tf32r(b1.x), tf32r(b1.y), tf32r(b1.z), tf32r(b1.w)};
        *(float4*)&Bs[0][brow][bcol]     = c0;
        *(float4*)&Bs[0][brow][bcol + 4] = c1;
    }
    __syncthreads();

    const int nT = kLen >> 4;
    for (int t = 0; t < nT; ++t) {
        const int buf = t & 1;
        const bool more = (t + 1 < nT);
        float4 a0, a1, b0, b1;
        if (more) {
            a0 = *(const float4*)(Ap + (t + 1) * 16);
            a1 = *(const float4*)(Ap + (t + 1) * 16 + 4);
            b0 = *(const float4*)(Wp + (size_t)(t + 1) * 16 * ldw);
            b1 = *(const float4*)(Wp + (size_t)(t + 1) * 16 * ldw + 4);
        }

        #pragma unroll
        for (int k8 = 0; k8 < 16; k8 += 8) {
            uint32_t af[4][4];
            uint32_t bf[4][2];
            #pragma unroll
            for (int mt = 0; mt < 4; ++mt) {
                const int m0 = wm * 64 + mt * 16 + g;
                af[mt][0] = __float_as_uint(As[buf][k8 + tg][m0]);
                af[mt][1] = __float_as_uint(As[buf][k8 + tg][m0 + 8]);
                af[mt][2] = __float_as_uint(As[buf][k8 + tg + 4][m0]);
                af[mt][3] = __float_as_uint(As[buf][k8 + tg + 4][m0 + 8]);
            }
            #pragma unroll
            for (int nt = 0; nt < 4; ++nt) {
                const int n0 = wn * 32 + nt * 8 + g;
                bf[nt][0] = __float_as_uint(Bs[buf][k8 + tg][n0]);
                bf[nt][1] = __float_as_uint(Bs[buf][k8 + tg + 4][n0]);
            }
            #pragma unroll
            for (int mt = 0; mt < 4; ++mt)
                #pragma unroll
                for (int nt = 0; nt < 4; ++nt)
                    mma_tf32(acc[mt][nt], af[mt], bf[nt]);
        }

        if (more) {
            const int nb = buf ^ 1;
            As[nb][acol + 0][arow] = tf32r(a0.x);
            As[nb][acol + 1][arow] = tf32r(a0.y);
            As[nb][acol + 2][arow] = tf32r(a0.z);
            As[nb][acol + 3][arow] = tf32r(a0.w);
            As[nb][acol + 4][arow] = tf32r(a1.x);
            As[nb][acol + 5][arow] = tf32r(a1.y);
            As[nb][acol + 6][arow] = tf32r(a1.z);
            As[nb][acol + 7][arow] = tf32r(a1.w);
            float4 c0 = {tf32r(b0.x), tf32r(b0.y), tf32r(b0.z), tf32r(b0.w)};
            float4 c1 = {tf32r(b1.x), tf32r(b1.y), tf32r(b1.z), tf32r(b1.w)};
            *(float4*)&Bs[nb][brow][bcol]     = c0;
            *(float4*)&Bs[nb][brow][bcol + 4] = c1;
            __syncthreads();
        }
    }

    // epilogue: thread owns (rows g, g+8) x (cols 2tg, 2tg+1) per tile
    #pragma unroll
    for (int mt = 0; mt < 4; ++mt) {
        const int row0 = rowBase + wm * 64 + mt * 16 + g;
        #pragma unroll
        for (int nt = 0; nt < 4; ++nt) {
            const int col = colBase + wn * 32 + nt * 8 + 2 * tg;
            float b0 = 0.f, b1 = 0.f;
            if (HAS_BIAS) {
                float2 bv = *(const float2*)(bias + col);
                b0 = bv.x; b1 = bv.y;
            }
            float v0 = acc[mt][nt][0] + b0;
            float v1 = acc[mt][nt][1] + b1;
            float v2 = acc[mt][nt][2] + b0;
            float v3 = acc[mt][nt][3] + b1;
            if (RELU) {
                v0 = fmaxf(v0, 0.f); v1 = fmaxf(v1, 0.f);
                v2 = fmaxf(v2, 0.f); v3 = fmaxf(v3, 0.f);
            }
            float2 o0 = {v0, v1};
            float2 o1 = {v2, v3};
            *(float2*)(C + (size_t)row0 * ldc + col)       = o0;
            *(float2*)(C + (size_t)(row0 + 8) * ldc + col) = o1;
        }
    }
}

// ---------------- split-K combine: C = [relu](sum_z part[z] [+ bias]) ----------------
template <bool RELU, bool HAS_BIAS, int S>
__global__ void combine_k(const float* __restrict__ part,
                          const float* __restrict__ bias,
                          float* __restrict__ C,
                          int M, int N, int ldc) {
    const int idx = blockIdx.x * blockDim.x + threadIdx.x;
    const int nq = N >> 2;
    if (idx >= M * nq) return;
    const int row = idx / nq;
    const int c0  = (idx - row * nq) * 4;
    const size_t off = (size_t)row * N + c0;
    float4 s = *(const float4*)(part + off);
    #pragma unroll
    for (int z = 1; z < S; ++z) {
        float4 p = *(const float4*)(part + (size_t)z * M * N + off);
        s.x += p.x; s.y += p.y; s.z += p.z; s.w += p.w;
    }
    if (HAS_BIAS) {
        float4 b = *(const float4*)(bias + c0);
        s.x += b.x; s.y += b.y; s.z += b.z; s.w += b.w;
    }
    if (RELU) {
        s.x = fmaxf(s.x, 0.f); s.y = fmaxf(s.y, 0.f);
        s.z = fmaxf(s.z, 0.f); s.w = fmaxf(s.w, 0.f);
    }
    *(float4*)(C + (size_t)row * ldc + c0) = s;
}

// ---------------- out[b] = x3[b,:] . mw4 + mb4 ----------------
__global__ void final_kernel(const float* __restrict__ x3,
                             const float* __restrict__ mw4,
                             const float* __restrict__ mb4,
                             float* __restrict__ out) {
    int row  = blockIdx.x * 8 + (threadIdx.x >> 5);
    int lane = threadIdx.x & 31;
    const float* x = x3 + (size_t)row * D3_;
    float s = 0.f;
    #pragma unroll
    for (int k = lane; k < D3_; k += 32) s += x[k] * mw4[k];
    #pragma unroll
    for (int o = 16; o > 0; o >>= 1) s += __shfl_xor_sync(0xffffffffu, s, o);
    if (lane == 0) out[row] = s + mb4[0];
}

// ---------------- launch ----------------
extern "C" void kernel_launch(void* const* d_in, const int* in_sizes, int n_in,
                              void* d_out, int out_size) {
    const float* cand  = (const float*)d_in[0];
    const float* rated = (const float*)d_in[1];
    const float* um    = (const float*)d_in[2];
    const float* attw  = (const float*)d_in[3];
    // d_in[4] = att_b: cancels in the masked softmax, unused.
    const float* iw1 = (const float*)d_in[5];
    const float* ib1 = (const float*)d_in[6];
    const float* iw2 = (const float*)d_in[7];
    const float* ib2 = (const float*)d_in[8];
    const float* uw1 = (const float*)d_in[9];
    const float* ub1 = (const float*)d_in[10];
    const float* uw2 = (const float*)d_in[11];
    const float* ub2 = (const float*)d_in[12];
    const float* mw1 = (const float*)d_in[13];
    const float* mb1 = (const float*)d_in[14];
    const float* mw2 = (const float*)d_in[15];
    const float* mb2 = (const float*)d_in[16];
    const float* mw3 = (const float*)d_in[17];
    const float* mb3 = (const float*)d_in[18];
    const float* mw4 = (const float*)d_in[19];
    const float* mb4 = (const float*)d_in[20];
    float* out = (float*)d_out;

    float *rs, *w, *uf, *ih1, *uh1, *xcat, *x1, *x2, *x3, *part;
    cudaGetSymbolAddress((void**)&rs,   g_rs);
    cudaGetSymbolAddress((void**)&w,    g_w);
    cudaGetSymbolAddress((void**)&uf,   g_uf);
    cudaGetSymbolAddress((void**)&ih1,  g_ih1);
    cudaGetSymbolAddress((void**)&uh1,  g_uh1);
    cudaGetSymbolAddress((void**)&xcat, g_xcat);
    cudaGetSymbolAddress((void**)&x1,   g_x1);
    cudaGetSymbolAddress((void**)&x2,   g_x2);
    cudaGetSymbolAddress((void**)&x3,   g_x3);
    cudaGetSymbolAddress((void**)&part, g_part);

    rs_kernel<<<II / 8, 256>>>(rated, attw, rs);
    attw_kernel<<<BB, 256>>>(um, rs, w);

    // uf = w @ rated  (2048 x 512 x 4096), split-K=4
    { dim3 g(DD / 128, BB / 128, 4);
      gemm_tc<false, false, true><<<g, 256>>>(w, rated, nullptr, part, BB, DD, II, DD);
      int n4 = BB * DD / 4;
      combine_k<false, false, 4><<<(n4 + 255) / 256, 256>>>(part, nullptr, uf, BB, DD, DD); }

    // ih1 = relu(cand @ iw1 + ib1)  (2048 x 1024 x 512)
    { dim3 g((2 * IE_) / 128, BB / 128);
      gemm_tc<true, true, false><<<g, 256>>>(cand, iw1, ib1, ih1, BB, 2 * IE_, DD, 2 * IE_); }

    // item_emb = relu(ih1 @ iw2 + ib2) -> xcat[:, :512], split-K=2
    { dim3 g(IE_ / 128, BB / 128, 2);
      gemm_tc<false, false, true><<<g, 256>>>(ih1, iw2, nullptr, part, BB, IE_, 2 * IE_, IE_);
      int n4 = BB * IE_ / 4;
      combine_k<true, true, 2><<<(n4 + 255) / 256, 256>>>(part, ib2, xcat, BB, IE_, IE_ + UE_); }

    // uh1 = relu(uf @ uw1 + ub1)  (2048 x 2048 x 512)
    { dim3 g((2 * UE_) / 128, BB / 128);
      gemm_tc<true, true, false><<<g, 256>>>(uf, uw1, ub1, uh1, BB, 2 * UE_, DD, 2 * UE_); }

    // user_emb = relu(uh1 @ uw2 + ub2) -> xcat[:, 512:]
    { dim3 g(UE_ / 128, BB / 128);
      gemm_tc<true, true, false><<<g, 256>>>(uh1, uw2, ub2, xcat + IE_, BB, UE_, 2 * UE_, IE_ + UE_); }

    // x1 = relu(xcat @ mw1 + mb1)  (2048 x 1024 x 1536)
    { dim3 g(D1_ / 128, BB / 128);
      gemm_tc<true, true, false><<<g, 256>>>(xcat, mw1, mb1, x1, BB, D1_, IE_ + UE_, D1_); }

    // x2 = relu(x1 @ mw2 + mb2)  (2048 x 512 x 1024), split-K=2
    { dim3 g(D2_ / 128, BB / 128, 2);
      gemm_tc<false, false, true><<<g, 256>>>(x1, mw2, nullptr, part, BB, D2_, D1_, D2_);
      int n4 = BB * D2_ / 4;
      combine_k<true, true, 2><<<(n4 + 255) / 256, 256>>>(part, mb2, x2, BB, D2_, D2_); }

    // x3 = relu(x2 @ mw3 + mb3)  (2048 x 256 x 512), split-K=4
    { dim3 g(D3_ / 128, BB / 128, 4);
      gemm_tc<false, false, true><<<g, 256>>>(x2, mw3, nullptr, part, BB, D3_, D2_, D3_);
      int n4 = BB * D3_ / 4;
      combine_k<true, true, 4><<<(n4 + 255) / 256, 256>>>(part, mb3, x3, BB, D3_, D3_); }

    final_kernel<<<BB / 8, 256>>>(x3, mw4, mb4, out);
}

// round 4
// speedup vs baseline: 2.8520x; 1.0605x over previous
#include <cuda_runtime.h>
#include <cuda_bf16.h>
#include <math_constants.h>
#include <cstdint>

// Problem dims
#define BB   2048
#define II   4096
#define DD   512
#define IE_  512
#define UE_  1024
#define D1_  1024
#define D2_  512
#define D3_  256

// ---------------- scratch (alloc-free rule: __device__ globals) ----------------
__device__ float g_rs   [II];
__device__ float g_e    [II];                    // exp(rs - max(rs))
__device__ float g_s    [BB];                    // per-row 1/Z (0 if fully masked)
__device__ float g_uf   [(size_t)BB * DD];
__device__ float g_ih1  [(size_t)BB * (2*IE_)];
__device__ float g_uh1  [(size_t)BB * (2*UE_)];
__device__ float g_xcat [(size_t)BB * (IE_ + UE_)];
__device__ float g_x1   [(size_t)BB * D1_];
__device__ float g_x2   [(size_t)BB * D2_];
__device__ float g_x3   [(size_t)BB * D3_];
__device__ float g_part [(size_t)4 * BB * DD];   // split-K partials (16 MB, max over all uses)

// ---------------- helpers ----------------
__device__ __forceinline__ float tf32r(float x) {
    float y;
    asm("cvt.rna.tf32.f32 %0, %1;" : "=f"(y) : "f"(x));
    return y;
}

__device__ __forceinline__ void mma_tf32(float* c, const uint32_t* a, const uint32_t* b) {
    asm volatile(
        "mma.sync.aligned.m16n8k8.row.col.f32.tf32.tf32.f32 "
        "{%0,%1,%2,%3}, {%4,%5,%6,%7}, {%8,%9}, {%0,%1,%2,%3};"
        : "+f"(c[0]), "+f"(c[1]), "+f"(c[2]), "+f"(c[3])
        : "r"(a[0]), "r"(a[1]), "r"(a[2]), "r"(a[3]), "r"(b[0]), "r"(b[1]));
}

// ---------------- rs[i] = rated_items[i,:] . att_w[D:2D] ----------------
__global__ void rs_kernel(const float* __restrict__ rated,
                          const float* __restrict__ attw,
                          float* __restrict__ rs) {
    int row  = blockIdx.x * 8 + (threadIdx.x >> 5);
    int lane = threadIdx.x & 31;
    const float* r  = rated + (size_t)row * DD;
    const float* wr = attw + DD;
    float s = 0.f;
    #pragma unroll 4
    for (int k = lane; k < DD; k += 32) s += r[k] * wr[k];
    #pragma unroll
    for (int o = 16; o > 0; o >>= 1) s += __shfl_xor_sync(0xffffffffu, s, o);
    if (lane == 0) rs[row] = s;
}

// ---------------- e[i] = exp(rs[i] - max_j rs[j])  (single block) ----------------
// Using the GLOBAL max is safe: per-row softmax max <= global max, and
// w[b,i] = um*e[i]*s[b] with s[b] = 1/sum(masked e) is invariant to the shift.
__global__ void maxexp_kernel(const float* __restrict__ rs,
                              float* __restrict__ e) {
    __shared__ float red[1024];
    const int tid = threadIdx.x;
    float m = -CUDART_INF_F;
    for (int i = tid; i < II; i += 1024) m = fmaxf(m, rs[i]);
    red[tid] = m; __syncthreads();
    for (int s = 512; s > 0; s >>= 1) {
        if (tid < s) red[tid] = fmaxf(red[tid], red[tid + s]);
        __syncthreads();
    }
    m = red[0];
    for (int i = tid; i < II; i += 1024) e[i] = __expf(rs[i] - m);
}

// ---------------- s[b] = 1 / sum_{i: um[b,i]!=0} e[i]  (0 if empty) ----------------
__global__ void stats_kernel(const float* __restrict__ um,
                             const float* __restrict__ e,
                             float* __restrict__ srow) {
    __shared__ float red[256];
    const int b = blockIdx.x;
    const float* umr = um + (size_t)b * II;
    const int tid = threadIdx.x;
    float z = 0.f;
    for (int i = tid; i < II; i += 256)
        if (umr[i] != 0.0f) z += e[i];
    red[tid] = z; __syncthreads();
    for (int s = 128; s > 0; s >>= 1) {
        if (tid < s) red[tid] += red[tid + s];
        __syncthreads();
    }
    if (tid == 0) {
        float zz = red[0];
        srow[b] = (zz > 0.f) ? (1.f / zz) : 0.f;
    }
}

// ---------------- TF32 tensor-core GEMM: 128x128x16 tiles ----------------
// A: MxK row-major, W: KxN row-major. 256 threads = 8 warps (2m x 4n),
// warp tile 64x32 from m16n8k8 mma (4 m-tiles x 4 n-tiles).
// SPLITK: blockIdx.z selects K-chunk, raw partial to C + z*M*N (ld=N).
// FUSE_ATT: A element = A[row,k]*e[k]; epilogue scales row by srow[row]
// (legal under split-K: scaling each partial scales the sum).
template <bool RELU, bool HAS_BIAS, bool SPLITK, bool FUSE_ATT>
__global__ void __launch_bounds__(256, 2)
gemm_tc(const float* __restrict__ A,
        const float* __restrict__ W,
        const float* __restrict__ bias,
        float* __restrict__ C,
        int M, int N, int K, int ldc,
        const float* __restrict__ evec,
        const float* __restrict__ srow) {
    const int lda = K, ldw = N;
    int kBeg = 0, kLen = K;
    if (SPLITK) {
        kLen = K / gridDim.z;
        kBeg = blockIdx.z * kLen;
        C += (size_t)blockIdx.z * M * N;
        ldc = N;
    }

    __shared__ float As[2][16][136];
    __shared__ float Bs[2][16][136];

    const int tid  = threadIdx.x;
    const int warp = tid >> 5;
    const int lane = tid & 31;
    const int g    = lane >> 2;
    const int tg   = lane & 3;
    const int wm   = warp >> 2;
    const int wn   = warp & 3;
    const int rowBase = blockIdx.y * 128;
    const int colBase = blockIdx.x * 128;

    const int arow = tid >> 1;
    const int acol = (tid & 1) * 8;
    const int brow = tid >> 4;
    const int bcol = (tid & 15) * 8;

    const float* Ap = A + (size_t)(rowBase + arow) * lda + kBeg + acol;
    const float* Wp = W + (size_t)(kBeg + brow) * ldw + colBase + bcol;
    const float* Ep = FUSE_ATT ? (evec + kBeg + acol) : nullptr;

    float acc[4][4][4];
    #pragma unroll
    for (int mt = 0; mt < 4; ++mt)
        #pragma unroll
        for (int nt = 0; nt < 4; ++nt)
            #pragma unroll
            for (int r = 0; r < 4; ++r) acc[mt][nt][r] = 0.f;

    // preload tile 0
    {
        float4 a0 = *(const float4*)Ap;
        float4 a1 = *(const float4*)(Ap + 4);
        if (FUSE_ATT) {
            float4 e0 = *(const float4*)Ep;
            float4 e1 = *(const float4*)(Ep + 4);
            a0.x *= e0.x; a0.y *= e0.y; a0.z *= e0.z; a0.w *= e0.w;
            a1.x *= e1.x; a1.y *= e1.y; a1.z *= e1.z; a1.w *= e1.w;
        }
        float4 b0 = *(const float4*)Wp;
        float4 b1 = *(const float4*)(Wp + 4);
        As[0][acol + 0][arow] = tf32r(a0.x);
        As[0][acol + 1][arow] = tf32r(a0.y);
        As[0][acol + 2][arow] = tf32r(a0.z);
        As[0][acol + 3][arow] = tf32r(a0.w);
        As[0][acol + 4][arow] = tf32r(a1.x);
        As[0][acol + 5][arow] = tf32r(a1.y);
        As[0][acol + 6][arow] = tf32r(a1.z);
        As[0][acol + 7][arow] = tf32r(a1.w);
        float4 c0 = {tf32r(b0.x), tf32r(b0.y), tf32r(b0.z), tf32r(b0.w)};
        float4 c1 = {tf32r(b1.x), tf32r(b1.y), tf32r(b1.z), tf32r(b1.w)};
        *(float4*)&Bs[0][brow][bcol]     = c0;
        *(float4*)&Bs[0][brow][bcol + 4] = c1;
    }
    __syncthreads();

    const int nT = kLen >> 4;
    for (int t = 0; t < nT; ++t) {
        const int buf = t & 1;
        const bool more = (t + 1 < nT);
        float4 a0, a1, b0, b1;
        if (more) {
            a0 = *(const float4*)(Ap + (t + 1) * 16);
            a1 = *(const float4*)(Ap + (t + 1) * 16 + 4);
            if (FUSE_ATT) {
                float4 e0 = *(const float4*)(Ep + (t + 1) * 16);
                float4 e1 = *(const float4*)(Ep + (t + 1) * 16 + 4);
                a0.x *= e0.x; a0.y *= e0.y; a0.z *= e0.z; a0.w *= e0.w;
                a1.x *= e1.x; a1.y *= e1.y; a1.z *= e1.z; a1.w *= e1.w;
            }
            b0 = *(const float4*)(Wp + (size_t)(t + 1) * 16 * ldw);
            b1 = *(const float4*)(Wp + (size_t)(t + 1) * 16 * ldw + 4);
        }

        #pragma unroll
        for (int k8 = 0; k8 < 16; k8 += 8) {
            uint32_t af[4][4];
            uint32_t bf[4][2];
            #pragma unroll
            for (int mt = 0; mt < 4; ++mt) {
                const int m0 = wm * 64 + mt * 16 + g;
                af[mt][0] = __float_as_uint(As[buf][k8 + tg][m0]);
                af[mt][1] = __float_as_uint(As[buf][k8 + tg][m0 + 8]);
                af[mt][2] = __float_as_uint(As[buf][k8 + tg + 4][m0]);
                af[mt][3] = __float_as_uint(As[buf][k8 + tg + 4][m0 + 8]);
            }
            #pragma unroll
            for (int nt = 0; nt < 4; ++nt) {
                const int n0 = wn * 32 + nt * 8 + g;
                bf[nt][0] = __float_as_uint(Bs[buf][k8 + tg][n0]);
                bf[nt][1] = __float_as_uint(Bs[buf][k8 + tg + 4][n0]);
            }
            #pragma unroll
            for (int mt = 0; mt < 4; ++mt)
                #pragma unroll
                for (int nt = 0; nt < 4; ++nt)
                    mma_tf32(acc[mt][nt], af[mt], bf[nt]);
        }

        if (more) {
            const int nb = buf ^ 1;
            As[nb][acol + 0][arow] = tf32r(a0.x);
            As[nb][acol + 1][arow] = tf32r(a0.y);
            As[nb][acol + 2][arow] = tf32r(a0.z);
            As[nb][acol + 3][arow] = tf32r(a0.w);
            As[nb][acol + 4][arow] = tf32r(a1.x);
            As[nb][acol + 5][arow] = tf32r(a1.y);
            As[nb][acol + 6][arow] = tf32r(a1.z);
            As[nb][acol + 7][arow] = tf32r(a1.w);
            float4 c0 = {tf32r(b0.x), tf32r(b0.y), tf32r(b0.z), tf32r(b0.w)};
            float4 c1 = {tf32r(b1.x), tf32r(b1.y), tf32r(b1.z), tf32r(b1.w)};
            *(float4*)&Bs[nb][brow][bcol]     = c0;
            *(float4*)&Bs[nb][brow][bcol + 4] = c1;
            __syncthreads();
        }
    }

    // epilogue
    #pragma unroll
    for (int mt = 0; mt < 4; ++mt) {
        const int row0 = rowBase + wm * 64 + mt * 16 + g;
        float s0 = 1.f, s1 = 1.f;
        if (FUSE_ATT) { s0 = srow[row0]; s1 = srow[row0 + 8]; }
        #pragma unroll
        for (int nt = 0; nt < 4; ++nt) {
            const int col = colBase + wn * 32 + nt * 8 + 2 * tg;
            float b0 = 0.f, b1 = 0.f;
            if (HAS_BIAS) {
                float2 bv = *(const float2*)(bias + col);
                b0 = bv.x; b1 = bv.y;
            }
            float v0 = acc[mt][nt][0], v1 = acc[mt][nt][1];
            float v2 = acc[mt][nt][2], v3 = acc[mt][nt][3];
            if (FUSE_ATT) { v0 *= s0; v1 *= s0; v2 *= s1; v3 *= s1; }
            v0 += b0; v1 += b1; v2 += b0; v3 += b1;
            if (RELU) {
                v0 = fmaxf(v0, 0.f); v1 = fmaxf(v1, 0.f);
                v2 = fmaxf(v2, 0.f); v3 = fmaxf(v3, 0.f);
            }
            float2 o0 = {v0, v1};
            float2 o1 = {v2, v3};
            *(float2*)(C + (size_t)row0 * ldc + col)       = o0;
            *(float2*)(C + (size_t)(row0 + 8) * ldc + col) = o1;
        }
    }
}

// ---------------- split-K combine: C = [relu](sum_z part[z] [+ bias]) ----------------
template <bool RELU, bool HAS_BIAS, int S>
__global__ void combine_k(const float* __restrict__ part,
                          const float* __restrict__ bias,
                          float* __restrict__ C,
                          int M, int N, int ldc) {
    const int idx = blockIdx.x * blockDim.x + threadIdx.x;
    const int nq = N >> 2;
    if (idx >= M * nq) return;
    const int row = idx / nq;
    const int c0  = (idx - row * nq) * 4;
    const size_t off = (size_t)row * N + c0;
    float4 s = *(const float4*)(part + off);
    #pragma unroll
    for (int z = 1; z < S; ++z) {
        float4 p = *(const float4*)(part + (size_t)z * M * N + off);
        s.x += p.x; s.y += p.y; s.z += p.z; s.w += p.w;
    }
    if (HAS_BIAS) {
        float4 b = *(const float4*)(bias + c0);
        s.x += b.x; s.y += b.y; s.z += b.z; s.w += b.w;
    }
    if (RELU) {
        s.x = fmaxf(s.x, 0.f); s.y = fmaxf(s.y, 0.f);
        s.z = fmaxf(s.z, 0.f); s.w = fmaxf(s.w, 0.f);
    }
    *(float4*)(C + (size_t)row * ldc + c0) = s;
}

// ---------------- out[b] = x3[b,:] . mw4 + mb4 ----------------
__global__ void final_kernel(const float* __restrict__ x3,
                             const float* __restrict__ mw4,
                             const float* __restrict__ mb4,
                             float* __restrict__ out) {
    int row  = blockIdx.x * 8 + (threadIdx.x >> 5);
    int lane = threadIdx.x & 31;
    const float* x = x3 + (size_t)row * D3_;
    float s = 0.f;
    #pragma unroll
    for (int k = lane; k < D3_; k += 32) s += x[k] * mw4[k];
    #pragma unroll
    for (int o = 16; o > 0; o >>= 1) s += __shfl_xor_sync(0xffffffffu, s, o);
    if (lane == 0) out[row] = s + mb4[0];
}

// ---------------- launch ----------------
extern "C" void kernel_launch(void* const* d_in, const int* in_sizes, int n_in,
                              void* d_out, int out_size) {
    const float* cand  = (const float*)d_in[0];
    const float* rated = (const float*)d_in[1];
    const float* um    = (const float*)d_in[2];
    const float* attw  = (const float*)d_in[3];
    // d_in[4] = att_b: cancels in the masked softmax, unused.
    const float* iw1 = (const float*)d_in[5];
    const float* ib1 = (const float*)d_in[6];
    const float* iw2 = (const float*)d_in[7];
    const float* ib2 = (const float*)d_in[8];
    const float* uw1 = (const float*)d_in[9];
    const float* ub1 = (const float*)d_in[10];
    const float* uw2 = (const float*)d_in[11];
    const float* ub2 = (const float*)d_in[12];
    const float* mw1 = (const float*)d_in[13];
    const float* mb1 = (const float*)d_in[14];
    const float* mw2 = (const float*)d_in[15];
    const float* mb2 = (const float*)d_in[16];
    const float* mw3 = (const float*)d_in[17];
    const float* mb3 = (const float*)d_in[18];
    const float* mw4 = (const float*)d_in[19];
    const float* mb4 = (const float*)d_in[20];
    float* out = (float*)d_out;

    float *rs, *e, *sB, *uf, *ih1, *uh1, *xcat, *x1, *x2, *x3, *part;
    cudaGetSymbolAddress((void**)&rs,   g_rs);
    cudaGetSymbolAddress((void**)&e,    g_e);
    cudaGetSymbolAddress((void**)&sB,   g_s);
    cudaGetSymbolAddress((void**)&uf,   g_uf);
    cudaGetSymbolAddress((void**)&ih1,  g_ih1);
    cudaGetSymbolAddress((void**)&uh1,  g_uh1);
    cudaGetSymbolAddress((void**)&xcat, g_xcat);
    cudaGetSymbolAddress((void**)&x1,   g_x1);
    cudaGetSymbolAddress((void**)&x2,   g_x2);
    cudaGetSymbolAddress((void**)&x3,   g_x3);
    cudaGetSymbolAddress((void**)&part, g_part);

    rs_kernel<<<II / 8, 256>>>(rated, attw, rs);
    maxexp_kernel<<<1, 1024>>>(rs, e);
    stats_kernel<<<BB, 256>>>(um, e, sB);

    // uf = (um .* e) @ rated, row-scaled by s  (2048 x 512 x 4096), splitK=4
    { dim3 g(DD / 128, BB / 128, 4);
      gemm_tc<false, false, true, true><<<g, 256>>>(um, rated, nullptr, part,
                                                    BB, DD, II, DD, e, sB);
      int n4 = BB * DD / 4;
      combine_k<false, false, 4><<<(n4 + 255) / 256, 256>>>(part, nullptr, uf, BB, DD, DD); }

    // ih1 = relu(cand @ iw1 + ib1)  (2048 x 1024 x 512), splitK=2 -> 256 CTAs
    { dim3 g((2 * IE_) / 128, BB / 128, 2);
      gemm_tc<false, false, true, false><<<g, 256>>>(cand, iw1, nullptr, part,
                                                     BB, 2 * IE_, DD, 0, nullptr, nullptr);
      int n4 = BB * (2 * IE_) / 4;
      combine_k<true, true, 2><<<(n4 + 255) / 256, 256>>>(part, ib1, ih1, BB, 2 * IE_, 2 * IE_); }

    // item_emb = relu(ih1 @ iw2 + ib2) -> xcat[:, :512], splitK=4 -> 256 CTAs
    { dim3 g(IE_ / 128, BB / 128, 4);
      gemm_tc<false, false, true, false><<<g, 256>>>(ih1, iw2, nullptr, part,
                                                     BB, IE_, 2 * IE_, 0, nullptr, nullptr);
      int n4 = BB * IE_ / 4;
      combine_k<true, true, 4><<<(n4 + 255) / 256, 256>>>(part, ib2, xcat, BB, IE_, IE_ + UE_); }

    // uh1 = relu(uf @ uw1 + ub1)  (2048 x 2048 x 512), 256 CTAs unsplit
    { dim3 g((2 * UE_) / 128, BB / 128);
      gemm_tc<true, true, false, false><<<g, 256>>>(uf, uw1, ub1, uh1,
                                                    BB, 2 * UE_, DD, 2 * UE_, nullptr, nullptr); }

    // user_emb = relu(uh1 @ uw2 + ub2) -> xcat[:, 512:], splitK=2 -> 256 CTAs
    { dim3 g(UE_ / 128, BB / 128, 2);
      gemm_tc<false, false, true, false><<<g, 256>>>(uh1, uw2, nullptr, part,
                                                     BB, UE_, 2 * UE_, 0, nullptr, nullptr);
      int n4 = BB * UE_ / 4;
      combine_k<true, true, 2><<<(n4 + 255) / 256, 256>>>(part, ub2, xcat + IE_, BB, UE_, IE_ + UE_); }

    // x1 = relu(xcat @ mw1 + mb1)  (2048 x 1024 x 1536), splitK=2 -> 256 CTAs
    { dim3 g(D1_ / 128, BB / 128, 2);
      gemm_tc<false, false, true, false><<<g, 256>>>(xcat, mw1, nullptr, part,
                                                     BB, D1_, IE_ + UE_, 0, nullptr, nullptr);
      int n4 = BB * D1_ / 4;
      combine_k<true, true, 2><<<(n4 + 255) / 256, 256>>>(part, mb1, x1, BB, D1_, D1_); }

    // x2 = relu(x1 @ mw2 + mb2)  (2048 x 512 x 1024), splitK=4 -> 256 CTAs
    { dim3 g(D2_ / 128, BB / 128, 4);
      gemm_tc<false, false, true, false><<<g, 256>>>(x1, mw2, nullptr, part,
                                                     BB, D2_, D1_, 0, nullptr, nullptr);
      int n4 = BB * D2_ / 4;
      combine_k<true, true, 4><<<(n4 + 255) / 256, 256>>>(part, mb2, x2, BB, D2_, D2_); }

    // x3 = relu(x2 @ mw3 + mb3)  (2048 x 256 x 512), splitK=8 -> 256 CTAs
    { dim3 g(D3_ / 128, BB / 128, 8);
      gemm_tc<false, false, true, false><<<g, 256>>>(x2, mw3, nullptr, part,
                                                     BB, D3_, D2_, 0, nullptr, nullptr);
      int n4 = BB * D3_ / 4;
      combine_k<true, true, 8><<<(n4 + 255) / 256, 256>>>(part, mb3, x3, BB, D3_, D3_); }

    final_kernel<<<BB / 8, 256>>>(x3, mw4, mb4, out);
}

// round 5
// speedup vs baseline: 3.2893x; 1.1533x over previous
#include <cuda_runtime.h>
#include <math_constants.h>
#include <cstdint>

// Problem dims
#define BB   2048
#define II   4096
#define DD   512
#define IE_  512
#define UE_  1024
#define D1_  1024
#define D2_  512
#define D3_  256

// ---------------- scratch (alloc-free rule: __device__ globals) ----------------
__device__ float g_rs    [II];
__device__ float g_e     [II];
__device__ float g_s     [BB];
__device__ float g_umr   [(size_t)BB * II];        // tf32(um * e)
__device__ float g_ratedr[(size_t)II * DD];
__device__ float g_candr [(size_t)BB * DD];
__device__ float g_iw1r  [DD * 2 * IE_];
__device__ float g_iw2r  [2 * IE_ * IE_];
__device__ float g_uw1r  [DD * 2 * UE_];
__device__ float g_uw2r  [2 * UE_ * UE_];
__device__ float g_mw1r  [(IE_ + UE_) * D1_];
__device__ float g_mw2r  [D1_ * D2_];
__device__ float g_mw3r  [D2_ * D3_];
__device__ float g_uf    [(size_t)BB * DD];
__device__ float g_ih1   [(size_t)BB * 2 * IE_];
__device__ float g_uh1   [(size_t)BB * 2 * UE_];
__device__ float g_xcat  [(size_t)BB * (IE_ + UE_)];
__device__ float g_x1    [(size_t)BB * D1_];
__device__ float g_x2    [(size_t)BB * D2_];
__device__ float g_x3    [(size_t)BB * D3_];
__device__ float g_part  [(size_t)4 * BB * DD];    // all splitK uses = 4M floats exactly

// ---------------- helpers ----------------
__device__ __forceinline__ float tf32r(float x) {
    float y;
    asm("cvt.rna.tf32.f32 %0, %1;" : "=f"(y) : "f"(x));
    return y;
}
__device__ __forceinline__ void mma_tf32(float* c, const uint32_t* a, const uint32_t* b) {
    asm volatile(
        "mma.sync.aligned.m16n8k8.row.col.f32.tf32.tf32.f32 "
        "{%0,%1,%2,%3}, {%4,%5,%6,%7}, {%8,%9}, {%0,%1,%2,%3};"
        : "+f"(c[0]), "+f"(c[1]), "+f"(c[2]), "+f"(c[3])
        : "r"(a[0]), "r"(a[1]), "r"(a[2]), "r"(a[3]), "r"(b[0]), "r"(b[1]));
}
__device__ __forceinline__ uint32_t smem_u32(const void* p) {
    return (uint32_t)__cvta_generic_to_shared(p);
}
__device__ __forceinline__ void ldsm4(uint32_t* r, uint32_t a) {
    asm volatile("ldmatrix.sync.aligned.m8n8.x4.shared.b16 {%0,%1,%2,%3}, [%4];"
                 : "=r"(r[0]), "=r"(r[1]), "=r"(r[2]), "=r"(r[3]) : "r"(a));
}
__device__ __forceinline__ void cpa16(uint32_t d, const void* s) {
    asm volatile("cp.async.ca.shared.global [%0], [%1], 16;" :: "r"(d), "l"(s));
}
#define CP_COMMIT asm volatile("cp.async.commit_group;")
#define CP_WAIT1  asm volatile("cp.async.wait_group 1;")
#define CP_WAIT0  asm volatile("cp.async.wait_group 0;")

// ---------------- elementwise tf32 rounding passes ----------------
__global__ void round_kernel(const float* __restrict__ in, float* __restrict__ out, int n4) {
    int i = blockIdx.x * blockDim.x + threadIdx.x;
    if (i >= n4) return;
    float4 v = ((const float4*)in)[i];
    v.x = tf32r(v.x); v.y = tf32r(v.y); v.z = tf32r(v.z); v.w = tf32r(v.w);
    ((float4*)out)[i] = v;
}
// umr[b,i] = tf32(um[b,i] * e[i])
__global__ void umscale_kernel(const float* __restrict__ um, const float* __restrict__ e,
                               float* __restrict__ out) {
    int i = blockIdx.x * blockDim.x + threadIdx.x;   // float4 index over BB*II/4
    float4 u = ((const float4*)um)[i];
    float4 ev = ((const float4*)e)[i & (II / 4 - 1)];
    u.x = tf32r(u.x * ev.x); u.y = tf32r(u.y * ev.y);
    u.z = tf32r(u.z * ev.z); u.w = tf32r(u.w * ev.w);
    ((float4*)out)[i] = u;
}

// ---------------- rs[i] = rated_items[i,:] . att_w[D:2D] ----------------
__global__ void rs_kernel(const float* __restrict__ rated,
                          const float* __restrict__ attw,
                          float* __restrict__ rs) {
    int row  = blockIdx.x * 8 + (threadIdx.x >> 5);
    int lane = threadIdx.x & 31;
    const float* r  = rated + (size_t)row * DD;
    const float* wr = attw + DD;
    float s = 0.f;
    #pragma unroll 4
    for (int k = lane; k < DD; k += 32) s += r[k] * wr[k];
    #pragma unroll
    for (int o = 16; o > 0; o >>= 1) s += __shfl_xor_sync(0xffffffffu, s, o);
    if (lane == 0) rs[row] = s;
}

// ---------------- e[i] = exp(rs[i] - max_j rs[j])  (global max is valid shift) ----------------
__global__ void maxexp_kernel(const float* __restrict__ rs, float* __restrict__ e) {
    __shared__ float red[1024];
    const int tid = threadIdx.x;
    float m = -CUDART_INF_F;
    for (int i = tid; i < II; i += 1024) m = fmaxf(m, rs[i]);
    red[tid] = m; __syncthreads();
    for (int s = 512; s > 0; s >>= 1) {
        if (tid < s) red[tid] = fmaxf(red[tid], red[tid + s]);
        __syncthreads();
    }
    m = red[0];
    for (int i = tid; i < II; i += 1024) e[i] = __expf(rs[i] - m);
}

// ---------------- s[b] = 1 / sum_{i: um[b,i]!=0} e[i]  (0 if empty) ----------------
__global__ void stats_kernel(const float* __restrict__ um, const float* __restrict__ e,
                             float* __restrict__ srow) {
    __shared__ float red[256];
    const int b = blockIdx.x;
    const float* umr = um + (size_t)b * II;
    const int tid = threadIdx.x;
    float z = 0.f;
    for (int i = tid; i < II; i += 256)
        if (umr[i] != 0.0f) z += e[i];
    red[tid] = z; __syncthreads();
    for (int s = 128; s > 0; s >>= 1) {
        if (tid < s) red[tid] += red[tid + s];
        __syncthreads();
    }
    if (tid == 0) {
        float zz = red[0];
        srow[b] = (zz > 0.f) ? (1.f / zz) : 0.f;
    }
}

// ---------------- TF32 TC GEMM: 128x128x16, cp.async + ldmatrix ----------------
// Operands MUST be pre-rounded to tf32 (HW truncation is then exact).
// A: MxK row-major, W: KxN row-major. 8 warps (2m x 4n), warp tile 64x32.
// SPLITK: blockIdx.z K-chunk -> raw partial at C + z*M*N (ld=N).
#define KT   16
#define APAD 20
#define BPAD 136

template <bool RELU, bool HAS_BIAS, bool SPLITK, bool ROUND>
__global__ void __launch_bounds__(256, 2)
gemm_tc(const float* __restrict__ A,
        const float* __restrict__ W,
        const float* __restrict__ bias,
        float* __restrict__ C,
        int M, int N, int K, int ldc) {
    const int lda = K, ldw = N;
    int kBeg = 0, kLen = K;
    if (SPLITK) {
        kLen = K / gridDim.z;
        kBeg = blockIdx.z * kLen;
        C += (size_t)blockIdx.z * M * N;
        ldc = N;
    }

    __shared__ __align__(16) float As[2][128][APAD];
    __shared__ __align__(16) float Bs[2][KT][BPAD];

    const int tid  = threadIdx.x;
    const int warp = tid >> 5;
    const int lane = tid & 31;
    const int g  = lane >> 2;
    const int tg = lane & 3;
    const int wm = warp >> 2;
    const int wn = warp & 3;
    const int rowBase = blockIdx.y * 128;
    const int colBase = blockIdx.x * 128;

    // cp.async chunk assignment: A 512 chunks (row=c>>2, kc=c&3), B 512 chunks (row=c>>5, nc=c&31)
    const int ar0 = tid >> 2,          akc = (tid & 3) * 4;
    const int ar1 = (tid + 256) >> 2;
    const int br0 = tid >> 5,          bnc = (tid & 31) * 4;
    const int br1 = (tid + 256) >> 5;

    const float* Apg0 = A + (size_t)(rowBase + ar0) * lda + kBeg + akc;
    const float* Apg1 = A + (size_t)(rowBase + ar1) * lda + kBeg + akc;
    const float* Wpg0 = W + (size_t)(kBeg + br0) * ldw + colBase + bnc;
    const float* Wpg1 = W + (size_t)(kBeg + br1) * ldw + colBase + bnc;

    const uint32_t sA = smem_u32(&As[0][0][0]);
    const uint32_t sB = smem_u32(&Bs[0][0][0]);
    const uint32_t dA0 = sA + (ar0 * APAD + akc) * 4;
    const uint32_t dA1 = sA + (ar1 * APAD + akc) * 4;
    const uint32_t dB0 = sB + (br0 * BPAD + bnc) * 4;
    const uint32_t dB1 = sB + (br1 * BPAD + bnc) * 4;
    const uint32_t aStride = 128 * APAD * 4;
    const uint32_t bStride = KT * BPAD * 4;

    // ldmatrix lane address: tiles a0..a3 = (m0..+7,k8..+3),(m0+8..+15,k8..+3),(..,k8+4..),(..,k8+4..)
    const int lm8 = lane & 7, sel = lane >> 3;
    const int lrow = wm * 64 + (sel & 1) * 8 + lm8;
    const int lcol = (sel >> 1) * 4;
    const uint32_t aFragBase = sA + (lrow * APAD + lcol) * 4;

    float acc[4][4][4];
    #pragma unroll
    for (int mt = 0; mt < 4; ++mt)
        #pragma unroll
        for (int nt = 0; nt < 4; ++nt)
            #pragma unroll
            for (int r = 0; r < 4; ++r) acc[mt][nt][r] = 0.f;

    // prologue: stage 0
    cpa16(dA0, Apg0); cpa16(dA1, Apg1);
    cpa16(dB0, Wpg0); cpa16(dB1, Wpg1);
    CP_COMMIT;

    const int nT = kLen / KT;
    for (int t = 0; t < nT; ++t) {
        const int buf = t & 1;
        if (t + 1 < nT) {
            const uint32_t nb = (uint32_t)((t + 1) & 1);
            cpa16(dA0 + nb * aStride, Apg0 + (t + 1) * KT);
            cpa16(dA1 + nb * aStride, Apg1 + (t + 1) * KT);
            cpa16(dB0 + nb * bStride, Wpg0 + (size_t)(t + 1) * KT * ldw);
            cpa16(dB1 + nb * bStride, Wpg1 + (size_t)(t + 1) * KT * ldw);
            CP_COMMIT;
            CP_WAIT1;
        } else {
            CP_WAIT0;
        }
        __syncthreads();

        #pragma unroll
        for (int k8 = 0; k8 < KT; k8 += 8) {
            uint32_t af[4][4];
            uint32_t bf[4][2];
            #pragma unroll
            for (int mt = 0; mt < 4; ++mt)
                ldsm4(af[mt], aFragBase + (uint32_t)buf * aStride + (mt * 16 * APAD + k8) * 4);
            #pragma unroll
            for (int nt = 0; nt < 4; ++nt) {
                const int n0 = wn * 32 + nt * 8 + g;
                bf[nt][0] = __float_as_uint(Bs[buf][k8 + tg][n0]);
                bf[nt][1] = __float_as_uint(Bs[buf][k8 + tg + 4][n0]);
            }
            #pragma unroll
            for (int mt = 0; mt < 4; ++mt)
                #pragma unroll
                for (int nt = 0; nt < 4; ++nt)
                    mma_tf32(acc[mt][nt], af[mt], bf[nt]);
        }
        __syncthreads();
    }

    // epilogue
    #pragma unroll
    for (int mt = 0; mt < 4; ++mt) {
        const int row0 = rowBase + wm * 64 + mt * 16 + g;
        #pragma unroll
        for (int nt = 0; nt < 4; ++nt) {
            const int col = colBase + wn * 32 + nt * 8 + 2 * tg;
            float b0 = 0.f, b1 = 0.f;
            if (HAS_BIAS) {
                float2 bv = *(const float2*)(bias + col);
                b0 = bv.x; b1 = bv.y;
            }
            float v0 = acc[mt][nt][0] + b0, v1 = acc[mt][nt][1] + b1;
            float v2 = acc[mt][nt][2] + b0, v3 = acc[mt][nt][3] + b1;
            if (RELU) {
                v0 = fmaxf(v0, 0.f); v1 = fmaxf(v1, 0.f);
                v2 = fmaxf(v2, 0.f); v3 = fmaxf(v3, 0.f);
            }
            if (ROUND) {
                v0 = tf32r(v0); v1 = tf32r(v1);
                v2 = tf32r(v2); v3 = tf32r(v3);
            }
            float2 o0 = {v0, v1};
            float2 o1 = {v2, v3};
            *(float2*)(C + (size_t)row0 * ldc + col)       = o0;
            *(float2*)(C + (size_t)(row0 + 8) * ldc + col) = o1;
        }
    }
}

// ---------------- split-K combine ----------------
template <bool RELU, bool HAS_BIAS, int S, bool SCALE_ROW, bool ROUND>
__global__ void combine_k(const float* __restrict__ part,
                          const float* __restrict__ bias,
                          const float* __restrict__ srow,
                          float* __restrict__ C,
                          int M, int N, int ldc) {
    const int idx = blockIdx.x * blockDim.x + threadIdx.x;
    const int nq = N >> 2;
    if (idx >= M * nq) return;
    const int row = idx / nq;
    const int c0  = (idx - row * nq) * 4;
    const size_t off = (size_t)row * N + c0;
    float4 s = *(const float4*)(part + off);
    #pragma unroll
    for (int z = 1; z < S; ++z) {
        float4 p = *(const float4*)(part + (size_t)z * M * N + off);
        s.x += p.x; s.y += p.y; s.z += p.z; s.w += p.w;
    }
    if (SCALE_ROW) {
        float sc = srow[row];
        s.x *= sc; s.y *= sc; s.z *= sc; s.w *= sc;
    }
    if (HAS_BIAS) {
        float4 b = *(const float4*)(bias + c0);
        s.x += b.x; s.y += b.y; s.z += b.z; s.w += b.w;
    }
    if (RELU) {
        s.x = fmaxf(s.x, 0.f); s.y = fmaxf(s.y, 0.f);
        s.z = fmaxf(s.z, 0.f); s.w = fmaxf(s.w, 0.f);
    }
    if (ROUND) {
        s.x = tf32r(s.x); s.y = tf32r(s.y); s.z = tf32r(s.z); s.w = tf32r(s.w);
    }
    *(float4*)(C + (size_t)row * ldc + c0) = s;
}

// ---------------- out[b] = x3[b,:] . mw4 + mb4 ----------------
__global__ void final_kernel(const float* __restrict__ x3,
                             const float* __restrict__ mw4,
                             const float* __restrict__ mb4,
                             float* __restrict__ out) {
    int row  = blockIdx.x * 8 + (threadIdx.x >> 5);
    int lane = threadIdx.x & 31;
    const float* x = x3 + (size_t)row * D3_;
    float s = 0.f;
    #pragma unroll
    for (int k = lane; k < D3_; k += 32) s += x[k] * mw4[k];
    #pragma unroll
    for (int o = 16; o > 0; o >>= 1) s += __shfl_xor_sync(0xffffffffu, s, o);
    if (lane == 0) out[row] = s + mb4[0];
}

// ---------------- launch ----------------
extern "C" void kernel_launch(void* const* d_in, const int* in_sizes, int n_in,
                              void* d_out, int out_size) {
    const float* cand  = (const float*)d_in[0];
    const float* rated = (const float*)d_in[1];
    const float* um    = (const float*)d_in[2];
    const float* attw  = (const float*)d_in[3];
    // d_in[4] = att_b: cancels in masked softmax, unused.
    const float* iw1 = (const float*)d_in[5];
    const float* ib1 = (const float*)d_in[6];
    const float* iw2 = (const float*)d_in[7];
    const float* ib2 = (const float*)d_in[8];
    const float* uw1 = (const float*)d_in[9];
    const float* ub1 = (const float*)d_in[10];
    const float* uw2 = (const float*)d_in[11];
    const float* ub2 = (const float*)d_in[12];
    const float* mw1 = (const float*)d_in[13];
    const float* mb1 = (const float*)d_in[14];
    const float* mw2 = (const float*)d_in[15];
    const float* mb2 = (const float*)d_in[16];
    const float* mw3 = (const float*)d_in[17];
    const float* mb3 = (const float*)d_in[18];
    const float* mw4 = (const float*)d_in[19];
    const float* mb4 = (const float*)d_in[20];
    float* out = (float*)d_out;

    float *rs, *e, *sB, *umr, *ratedr, *candr;
    float *iw1r, *iw2r, *uw1r, *uw2r, *mw1r, *mw2r, *mw3r;
    float *uf, *ih1, *uh1, *xcat, *x1, *x2, *x3, *part;
    cudaGetSymbolAddress((void**)&rs,     g_rs);
    cudaGetSymbolAddress((void**)&e,      g_e);
    cudaGetSymbolAddress((void**)&sB,     g_s);
    cudaGetSymbolAddress((void**)&umr,    g_umr);
    cudaGetSymbolAddress((void**)&ratedr, g_ratedr);
    cudaGetSymbolAddress((void**)&candr,  g_candr);
    cudaGetSymbolAddress((void**)&iw1r,   g_iw1r);
    cudaGetSymbolAddress((void**)&iw2r,   g_iw2r);
    cudaGetSymbolAddress((void**)&uw1r,   g_uw1r);
    cudaGetSymbolAddress((void**)&uw2r,   g_uw2r);
    cudaGetSymbolAddress((void**)&mw1r,   g_mw1r);
    cudaGetSymbolAddress((void**)&mw2r,   g_mw2r);
    cudaGetSymbolAddress((void**)&mw3r,   g_mw3r);
    cudaGetSymbolAddress((void**)&uf,     g_uf);
    cudaGetSymbolAddress((void**)&ih1,    g_ih1);
    cudaGetSymbolAddress((void**)&uh1,    g_uh1);
    cudaGetSymbolAddress((void**)&xcat,   g_xcat);
    cudaGetSymbolAddress((void**)&x1,     g_x1);
    cudaGetSymbolAddress((void**)&x2,     g_x2);
    cudaGetSymbolAddress((void**)&x3,     g_x3);
    cudaGetSymbolAddress((void**)&part,   g_part);

    auto roundN = [&](const float* in, float* outp, int nElems) {
        int n4 = nElems / 4;
        round_kernel<<<(n4 + 255) / 256, 256>>>(in, outp, n4);
    };

    // attention scalars
    rs_kernel<<<II / 8, 256>>>(rated, attw, rs);
    maxexp_kernel<<<1, 1024>>>(rs, e);
    stats_kernel<<<BB, 256>>>(um, e, sB);

    // pre-round operands (weights + inputs); activations rounded in epilogues
    umscale_kernel<<<(BB * II / 4 + 255) / 256, 256>>>(um, e, umr);
    roundN(rated, ratedr, II * DD);
    roundN(cand,  candr,  BB * DD);
    roundN(iw1, iw1r, DD * 2 * IE_);
    roundN(iw2, iw2r, 2 * IE_ * IE_);
    roundN(uw1, uw1r, DD * 2 * UE_);
    roundN(uw2, uw2r, 2 * UE_ * UE_);
    roundN(mw1, mw1r, (IE_ + UE_) * D1_);
    roundN(mw2, mw2r, D1_ * D2_);
    roundN(mw3, mw3r, D2_ * D3_);

    // uf = (umr) @ ratedr, row-scaled by s in combine  (2048x512x4096), splitK=4
    { dim3 g(DD / 128, BB / 128, 4);
      gemm_tc<false, false, true, false><<<g, 256>>>(umr, ratedr, nullptr, part, BB, DD, II, 0);
      int n4 = BB * DD / 4;
      combine_k<false, false, 4, true, true><<<(n4 + 255) / 256, 256>>>(part, nullptr, sB, uf, BB, DD, DD); }

    // ih1 = relu(candr @ iw1r + ib1)  splitK=2
    { dim3 g((2 * IE_) / 128, BB / 128, 2);
      gemm_tc<false, false, true, false><<<g, 256>>>(candr, iw1r, nullptr, part, BB, 2 * IE_, DD, 0);
      int n4 = BB * (2 * IE_) / 4;
      combine_k<true, true, 2, false, true><<<(n4 + 255) / 256, 256>>>(part, ib1, nullptr, ih1, BB, 2 * IE_, 2 * IE_); }

    // item_emb -> xcat[:, :512]  splitK=4
    { dim3 g(IE_ / 128, BB / 128, 4);
      gemm_tc<false, false, true, false><<<g, 256>>>(ih1, iw2r, nullptr, part, BB, IE_, 2 * IE_, 0);
      int n4 = BB * IE_ / 4;
      combine_k<true, true, 4, false, true><<<(n4 + 255) / 256, 256>>>(part, ib2, nullptr, xcat, BB, IE_, IE_ + UE_); }

    // uh1 = relu(uf @ uw1r + ub1)  (2048x2048x512), unsplit 256 CTAs
    { dim3 g((2 * UE_) / 128, BB / 128);
      gemm_tc<true, true, false, true><<<g, 256>>>(uf, uw1r, ub1, uh1, BB, 2 * UE_, DD, 2 * UE_); }

    // user_emb -> xcat[:, 512:]  splitK=2
    { dim3 g(UE_ / 128, BB / 128, 2);
      gemm_tc<false, false, true, false><<<g, 256>>>(uh1, uw2r, nullptr, part, BB, UE_, 2 * UE_, 0);
      int n4 = BB * UE_ / 4;
      combine_k<true, true, 2, false, true><<<(n4 + 255) / 256, 256>>>(part, ub2, nullptr, xcat + IE_, BB, UE_, IE_ + UE_); }

    // x1 = relu(xcat @ mw1r + mb1)  splitK=2
    { dim3 g(D1_ / 128, BB / 128, 2);
      gemm_tc<false, false, true, false><<<g, 256>>>(xcat, mw1r, nullptr, part, BB, D1_, IE_ + UE_, 0);
      int n4 = BB * D1_ / 4;
      combine_k<true, true, 2, false, true><<<(n4 + 255) / 256, 256>>>(part, mb1, nullptr, x1, BB, D1_, D1_); }

    // x2 = relu(x1 @ mw2r + mb2)  splitK=4
    { dim3 g(D2_ / 128, BB / 128, 4);
      gemm_tc<false, false, true, false><<<g, 256>>>(x1, mw2r, nullptr, part, BB, D2_, D1_, 0);
      int n4 = BB * D2_ / 4;
      combine_k<true, true, 4, false, true><<<(n4 + 255) / 256, 256>>>(part, mb2, nullptr, x2, BB, D2_, D2_); }

    // x3 = relu(x2 @ mw3r + mb3)  splitK=8 (no round: fp32 GEMV next)
    { dim3 g(D3_ / 128, BB / 128, 8);
      gemm_tc<false, false, true, false><<<g, 256>>>(x2, mw3r, nullptr, part, BB, D3_, D2_, 0);
      int n4 = BB * D3_ / 4;
      combine_k<true, true, 8, false, false><<<(n4 + 255) / 256, 256>>>(part, mb3, nullptr, x3, BB, D3_, D3_); }

    final_kernel<<<BB / 8, 256>>>(x3, mw4, mb4, out);
}

// round 6
// speedup vs baseline: 3.7335x; 1.1350x over previous
#include <cuda_runtime.h>
#include <math_constants.h>
#include <cstdint>

// Problem dims
#define BB   2048
#define II   4096
#define DD   512
#define IE_  512
#define UE_  1024
#define D1_  1024
#define D2_  512
#define D3_  256

// GEMM tiling
#define KT    16
#define APAD  20
#define BPAD  20
#define ASTG  (128 * APAD)          // floats per A stage
#define BSTG  (128 * BPAD)          // floats per B stage
#define STGF  (ASTG + BSTG)         // floats per stage
#define GEMM_SMEM (3 * STGF * 4)    // 61440 bytes

// ---------------- scratch (alloc-free rule: __device__ globals) ----------------
__device__ float g_rs    [II];
__device__ float g_e     [II];
__device__ float g_s     [BB];
__device__ float g_umr   [(size_t)BB * II];     // tf32(um * e)
__device__ float g_ratedT[(size_t)DD * II];     // tf32(rated)^T  [d][i]
__device__ float g_candr [(size_t)BB * DD];
__device__ float g_iw1t  [2 * IE_ * DD];
__device__ float g_iw2t  [IE_ * 2 * IE_];
__device__ float g_uw1t  [2 * UE_ * DD];
__device__ float g_uw2t  [UE_ * 2 * UE_];
__device__ float g_mw1t  [D1_ * (IE_ + UE_)];
__device__ float g_mw2t  [D2_ * D1_];
__device__ float g_mw3t  [D3_ * D2_];
__device__ float g_uf    [(size_t)BB * DD];
__device__ float g_ih1   [(size_t)BB * 2 * IE_];
__device__ float g_uh1   [(size_t)BB * 2 * UE_];
__device__ float g_xcat  [(size_t)BB * (IE_ + UE_)];
__device__ float g_x1    [(size_t)BB * D1_];
__device__ float g_x2    [(size_t)BB * D2_];
__device__ float g_x3    [(size_t)BB * D3_];
__device__ float g_part  [(size_t)4 * BB * DD]; // split-K partials (4M floats, max use)

// ---------------- helpers ----------------
__device__ __forceinline__ float tf32r(float x) {
    float y;
    asm("cvt.rna.tf32.f32 %0, %1;" : "=f"(y) : "f"(x));
    return y;
}
__device__ __forceinline__ void mma_tf32(float* c, const uint32_t* a, const uint32_t* b) {
    asm volatile(
        "mma.sync.aligned.m16n8k8.row.col.f32.tf32.tf32.f32 "
        "{%0,%1,%2,%3}, {%4,%5,%6,%7}, {%8,%9}, {%0,%1,%2,%3};"
        : "+f"(c[0]), "+f"(c[1]), "+f"(c[2]), "+f"(c[3])
        : "r"(a[0]), "r"(a[1]), "r"(a[2]), "r"(a[3]), "r"(b[0]), "r"(b[1]));
}
__device__ __forceinline__ uint32_t smem_u32(const void* p) {
    return (uint32_t)__cvta_generic_to_shared(p);
}
__device__ __forceinline__ void ldsm4(uint32_t* r, uint32_t a) {
    asm volatile("ldmatrix.sync.aligned.m8n8.x4.shared.b16 {%0,%1,%2,%3}, [%4];"
                 : "=r"(r[0]), "=r"(r[1]), "=r"(r[2]), "=r"(r[3]) : "r"(a));
}
__device__ __forceinline__ void cpa16(uint32_t d, const void* s) {
    asm volatile("cp.async.ca.shared.global [%0], [%1], 16;" :: "r"(d), "l"(s));
}
#define CP_COMMIT asm volatile("cp.async.commit_group;")
#define CP_WAITG1 asm volatile("cp.async.wait_group 1;")
#define CP_WAIT0  asm volatile("cp.async.wait_group 0;")

// ---------------- elementwise / pre-pass kernels ----------------
__global__ void round_kernel(const float* __restrict__ in, float* __restrict__ out, int n4) {
    int i = blockIdx.x * blockDim.x + threadIdx.x;
    if (i >= n4) return;
    float4 v = ((const float4*)in)[i];
    v.x = tf32r(v.x); v.y = tf32r(v.y); v.z = tf32r(v.z); v.w = tf32r(v.w);
    ((float4*)out)[i] = v;
}

// out[c][r] = tf32(in[r][c]);  in: R x C, block (32,8), grid (C/32, R/32)
__global__ void transpose_tf32(const float* __restrict__ in, float* __restrict__ out,
                               int R, int C) {
    __shared__ float t[32][33];
    const int bx = blockIdx.x * 32;   // col base
    const int by = blockIdx.y * 32;   // row base
    const int tx = threadIdx.x, ty = threadIdx.y;
    #pragma unroll
    for (int j = 0; j < 32; j += 8)
        t[ty + j][tx] = tf32r(in[(size_t)(by + ty + j) * C + bx + tx]);
    __syncthreads();
    #pragma unroll
    for (int j = 0; j < 32; j += 8)
        out[(size_t)(bx + ty + j) * R + by + tx] = t[tx][ty + j];
}

// fused: umr[b,i] = tf32(um[b,i]*e[i]);  srow[b] = 1/sum_{um!=0} e[i] (0 if none)
__global__ void umstats_kernel(const float* __restrict__ um, const float* __restrict__ e,
                               float* __restrict__ umr, float* __restrict__ srow) {
    __shared__ float red[256];
    const int b = blockIdx.x;
    const int tid = threadIdx.x;
    const float4* u4 = (const float4*)(um + (size_t)b * II);
    const float4* e4 = (const float4*)e;
    float4*       o4 = (float4*)(umr + (size_t)b * II);
    float z = 0.f;
    for (int i = tid; i < II / 4; i += 256) {
        float4 u = u4[i];
        float4 ev = e4[i];
        float4 o;
        o.x = tf32r(u.x * ev.x); o.y = tf32r(u.y * ev.y);
        o.z = tf32r(u.z * ev.z); o.w = tf32r(u.w * ev.w);
        if (u.x != 0.f) z += ev.x;
        if (u.y != 0.f) z += ev.y;
        if (u.z != 0.f) z += ev.z;
        if (u.w != 0.f) z += ev.w;
        o4[i] = o;
    }
    red[tid] = z; __syncthreads();
    for (int s = 128; s > 0; s >>= 1) {
        if (tid < s) red[tid] += red[tid + s];
        __syncthreads();
    }
    if (tid == 0) {
        float zz = red[0];
        srow[b] = (zz > 0.f) ? (1.f / zz) : 0.f;
    }
}

// ---------------- rs[i] = rated_items[i,:] . att_w[D:2D] ----------------
__global__ void rs_kernel(const float* __restrict__ rated,
                          const float* __restrict__ attw,
                          float* __restrict__ rs) {
    int row  = blockIdx.x * 8 + (threadIdx.x >> 5);
    int lane = threadIdx.x & 31;
    const float* r  = rated + (size_t)row * DD;
    const float* wr = attw + DD;
    float s = 0.f;
    #pragma unroll 4
    for (int k = lane; k < DD; k += 32) s += r[k] * wr[k];
    #pragma unroll
    for (int o = 16; o > 0; o >>= 1) s += __shfl_xor_sync(0xffffffffu, s, o);
    if (lane == 0) rs[row] = s;
}

// ---------------- e[i] = exp(rs[i] - max_j rs[j])  (global shift is valid) ----------------
__global__ void maxexp_kernel(const float* __restrict__ rs, float* __restrict__ e) {
    __shared__ float red[1024];
    const int tid = threadIdx.x;
    float m = -CUDART_INF_F;
    for (int i = tid; i < II; i += 1024) m = fmaxf(m, rs[i]);
    red[tid] = m; __syncthreads();
    for (int s = 512; s > 0; s >>= 1) {
        if (tid < s) red[tid] = fmaxf(red[tid], red[tid + s]);
        __syncthreads();
    }
    m = red[0];
    for (int i = tid; i < II; i += 1024) e[i] = __expf(rs[i] - m);
}

// ---------------- TF32 TC GEMM: 128x128x16, 3-stage cp.async, all-ldmatrix ----------------
// A: MxK row-major (pre-rounded tf32). Wt: NxK row-major (pre-rounded+transposed).
// 8 warps (2m x 4n), warp tile 64x32. One __syncthreads per k-tile.
// SPLITK: blockIdx.z K-chunk -> raw partial at C + z*M*N (ld=N).
template <bool RELU, bool HAS_BIAS, bool SPLITK, bool ROUND>
__global__ void __launch_bounds__(256, 2)
gemm_tc(const float* __restrict__ A,
        const float* __restrict__ Wt,
        const float* __restrict__ bias,
        float* __restrict__ C,
        int M, int N, int K, int ldc) {
    extern __shared__ float smemf[];
    int kBeg = 0, kLen = K;
    if (SPLITK) {
        kLen = K / gridDim.z;
        kBeg = blockIdx.z * kLen;
        C += (size_t)blockIdx.z * M * N;
        ldc = N;
    }

    const int tid  = threadIdx.x;
    const int warp = tid >> 5;
    const int lane = tid & 31;
    const int g  = lane >> 2;
    const int tg = lane & 3;
    const int wm = warp >> 2;
    const int wn = warp & 3;
    const int rowBase = blockIdx.y * 128;
    const int colBase = blockIdx.x * 128;

    // loaders: 128 rows x 16 floats per stage for both A and B(T)
    const int r0  = tid >> 2;            // 0..63
    const int kc  = (tid & 3) * 4;       // 0,4,8,12
    const int r1  = r0 + 64;

    const float* Ap0 = A  + (size_t)(rowBase + r0) * K + kBeg + kc;
    const float* Ap1 = A  + (size_t)(rowBase + r1) * K + kBeg + kc;
    const float* Wp0 = Wt + (size_t)(colBase + r0) * K + kBeg + kc;
    const float* Wp1 = Wt + (size_t)(colBase + r1) * K + kBeg + kc;

    const uint32_t sBase = smem_u32(smemf);
    const uint32_t dA0 = sBase + (r0 * APAD + kc) * 4;
    const uint32_t dA1 = sBase + (r1 * APAD + kc) * 4;
    const uint32_t dB0 = sBase + (ASTG + r0 * BPAD + kc) * 4;
    const uint32_t dB1 = sBase + (ASTG + r1 * BPAD + kc) * 4;

    // ldmatrix fragment base addresses
    const int lm8 = lane & 7, sel = lane >> 3;
    const uint32_t aFragBase = sBase +
        ((wm * 64 + (sel & 1) * 8 + lm8) * APAD + (sel >> 1) * 4) * 4;
    const uint32_t bFragBase = sBase +
        (ASTG + (wn * 32 + ((lane >> 4) & 1) * 8 + lm8) * BPAD + ((lane >> 3) & 1) * 4) * 4;

    float acc[4][4][4];
    #pragma unroll
    for (int mt = 0; mt < 4; ++mt)
        #pragma unroll
        for (int nt = 0; nt < 4; ++nt)
            #pragma unroll
            for (int r = 0; r < 4; ++r) acc[mt][nt][r] = 0.f;

    const int nT = kLen / KT;

    // prologue: stages 0 and 1
    {
        cpa16(dA0, Ap0); cpa16(dA1, Ap1); cpa16(dB0, Wp0); cpa16(dB1, Wp1);
        CP_COMMIT;
        if (nT > 1) {
            const uint32_t off = STGF * 4;
            cpa16(dA0 + off, Ap0 + KT); cpa16(dA1 + off, Ap1 + KT);
            cpa16(dB0 + off, Wp0 + KT); cpa16(dB1 + off, Wp1 + KT);
        }
        CP_COMMIT;
    }

    int cs = 0;  // compute slot = t % 3
    for (int t = 0; t < nT; ++t) {
        CP_WAITG1;          // stage t complete (only stage t+1 may remain)
        __syncthreads();    // data visible; slot (t+2)%3 free (read finished at t-1)

        if (t + 2 < nT) {
            const int is = (cs == 0) ? 2 : cs - 1;        // (t+2)%3
            const uint32_t off = (uint32_t)is * STGF * 4;
            const int ko = (t + 2) * KT;
            cpa16(dA0 + off, Ap0 + ko); cpa16(dA1 + off, Ap1 + ko);
            cpa16(dB0 + off, Wp0 + ko); cpa16(dB1 + off, Wp1 + ko);
        }
        CP_COMMIT;          // one group per iter (possibly empty) keeps accounting fixed

        const uint32_t off = (uint32_t)cs * STGF * 4;
        #pragma unroll
        for (int k8 = 0; k8 < KT; k8 += 8) {
            uint32_t af[4][4];
            uint32_t b01[4], b23[4];
            #pragma unroll
            for (int mt = 0; mt < 4; ++mt)
                ldsm4(af[mt], aFragBase + off + (mt * 16 * APAD + k8) * 4);
            ldsm4(b01, bFragBase + off + k8 * 4);                    // nt 0,1
            ldsm4(b23, bFragBase + off + (16 * BPAD + k8) * 4);      // nt 2,3
            uint32_t bf[4][2] = {{b01[0], b01[1]}, {b01[2], b01[3]},
                                 {b23[0], b23[1]}, {b23[2], b23[3]}};
            #pragma unroll
            for (int mt = 0; mt < 4; ++mt)
                #pragma unroll
                for (int nt = 0; nt < 4; ++nt)
                    mma_tf32(acc[mt][nt], af[mt], bf[nt]);
        }
        cs = (cs == 2) ? 0 : cs + 1;
    }
    CP_WAIT0;  // drain before exit

    // epilogue
    #pragma unroll
    for (int mt = 0; mt < 4; ++mt) {
        const int row0 = rowBase + wm * 64 + mt * 16 + g;
        #pragma unroll
        for (int nt = 0; nt < 4; ++nt) {
            const int col = colBase + wn * 32 + nt * 8 + 2 * tg;
            float b0 = 0.f, b1 = 0.f;
            if (HAS_BIAS) {
                float2 bv = *(const float2*)(bias + col);
                b0 = bv.x; b1 = bv.y;
            }
            float v0 = acc[mt][nt][0] + b0, v1 = acc[mt][nt][1] + b1;
            float v2 = acc[mt][nt][2] + b0, v3 = acc[mt][nt][3] + b1;
            if (RELU) {
                v0 = fmaxf(v0, 0.f); v1 = fmaxf(v1, 0.f);
                v2 = fmaxf(v2, 0.f); v3 = fmaxf(v3, 0.f);
            }
            if (ROUND) {
                v0 = tf32r(v0); v1 = tf32r(v1); v2 = tf32r(v2); v3 = tf32r(v3);
            }
            float2 o0 = {v0, v1};
            float2 o1 = {v2, v3};
            *(float2*)(C + (size_t)row0 * ldc + col)       = o0;
            *(float2*)(C + (size_t)(row0 + 8) * ldc + col) = o1;
        }
    }
}

// ---------------- split-K combine ----------------
template <bool RELU, bool HAS_BIAS, int S, bool SCALE_ROW, bool ROUND>
__global__ void combine_k(const float* __restrict__ part,
                          const float* __restrict__ bias,
                          const float* __restrict__ srow,
                          float* __restrict__ C,
                          int M, int N, int ldc) {
    const int idx = blockIdx.x * blockDim.x + threadIdx.x;
    const int nq = N >> 2;
    if (idx >= M * nq) return;
    const int row = idx / nq;
    const int c0  = (idx - row * nq) * 4;
    const size_t off = (size_t)row * N + c0;
    float4 s = *(const float4*)(part + off);
    #pragma unroll
    for (int z = 1; z < S; ++z) {
        float4 p = *(const float4*)(part + (size_t)z * M * N + off);
        s.x += p.x; s.y += p.y; s.z += p.z; s.w += p.w;
    }
    if (SCALE_ROW) {
        float sc = srow[row];
        s.x *= sc; s.y *= sc; s.z *= sc; s.w *= sc;
    }
    if (HAS_BIAS) {
        float4 b = *(const float4*)(bias + c0);
        s.x += b.x; s.y += b.y; s.z += b.z; s.w += b.w;
    }
    if (RELU) {
        s.x = fmaxf(s.x, 0.f); s.y = fmaxf(s.y, 0.f);
        s.z = fmaxf(s.z, 0.f); s.w = fmaxf(s.w, 0.f);
    }
    if (ROUND) {
        s.x = tf32r(s.x); s.y = tf32r(s.y); s.z = tf32r(s.z); s.w = tf32r(s.w);
    }
    *(float4*)(C + (size_t)row * ldc + c0) = s;
}

// ---------------- out[b] = x3[b,:] . mw4 + mb4 ----------------
__global__ void final_kernel(const float* __restrict__ x3,
                             const float* __restrict__ mw4,
                             const float* __restrict__ mb4,
                             float* __restrict__ out) {
    int row  = blockIdx.x * 8 + (threadIdx.x >> 5);
    int lane = threadIdx.x & 31;
    const float* x = x3 + (size_t)row * D3_;
    float s = 0.f;
    #pragma unroll
    for (int k = lane; k < D3_; k += 32) s += x[k] * mw4[k];
    #pragma unroll
    for (int o = 16; o > 0; o >>= 1) s += __shfl_xor_sync(0xffffffffu, s, o);
    if (lane == 0) out[row] = s + mb4[0];
}

// ---------------- launch ----------------
extern "C" void kernel_launch(void* const* d_in, const int* in_sizes, int n_in,
                              void* d_out, int out_size) {
    const float* cand  = (const float*)d_in[0];
    const float* rated = (const float*)d_in[1];
    const float* um    = (const float*)d_in[2];
    const float* attw  = (const float*)d_in[3];
    // d_in[4] = att_b: cancels in masked softmax, unused.
    const float* iw1 = (const float*)d_in[5];
    const float* ib1 = (const float*)d_in[6];
    const float* iw2 = (const float*)d_in[7];
    const float* ib2 = (const float*)d_in[8];
    const float* uw1 = (const float*)d_in[9];
    const float* ub1 = (const float*)d_in[10];
    const float* uw2 = (const float*)d_in[11];
    const float* ub2 = (const float*)d_in[12];
    const float* mw1 = (const float*)d_in[13];
    const float* mb1 = (const float*)d_in[14];
    const float* mw2 = (const float*)d_in[15];
    const float* mb2 = (const float*)d_in[16];
    const float* mw3 = (const float*)d_in[17];
    const float* mb3 = (const float*)d_in[18];
    const float* mw4 = (const float*)d_in[19];
    const float* mb4 = (const float*)d_in[20];
    float* out = (float*)d_out;

    float *rs, *e, *sB, *umr, *ratedT, *candr;
    float *iw1t, *iw2t, *uw1t, *uw2t, *mw1t, *mw2t, *mw3t;
    float *uf, *ih1, *uh1, *xcat, *x1, *x2, *x3, *part;
    cudaGetSymbolAddress((void**)&rs,     g_rs);
    cudaGetSymbolAddress((void**)&e,      g_e);
    cudaGetSymbolAddress((void**)&sB,     g_s);
    cudaGetSymbolAddress((void**)&umr,    g_umr);
    cudaGetSymbolAddress((void**)&ratedT, g_ratedT);
    cudaGetSymbolAddress((void**)&candr,  g_candr);
    cudaGetSymbolAddress((void**)&iw1t,   g_iw1t);
    cudaGetSymbolAddress((void**)&iw2t,   g_iw2t);
    cudaGetSymbolAddress((void**)&uw1t,   g_uw1t);
    cudaGetSymbolAddress((void**)&uw2t,   g_uw2t);
    cudaGetSymbolAddress((void**)&mw1t,   g_mw1t);
    cudaGetSymbolAddress((void**)&mw2t,   g_mw2t);
    cudaGetSymbolAddress((void**)&mw3t,   g_mw3t);
    cudaGetSymbolAddress((void**)&uf,     g_uf);
    cudaGetSymbolAddress((void**)&ih1,    g_ih1);
    cudaGetSymbolAddress((void**)&uh1,    g_uh1);
    cudaGetSymbolAddress((void**)&xcat,   g_xcat);
    cudaGetSymbolAddress((void**)&x1,     g_x1);
    cudaGetSymbolAddress((void**)&x2,     g_x2);
    cudaGetSymbolAddress((void**)&x3,     g_x3);
    cudaGetSymbolAddress((void**)&part,   g_part);

    // opt-in to 60KB dynamic smem for both GEMM instantiations
    cudaFuncSetAttribute((const void*)gemm_tc<false, false, true, false>,
                         cudaFuncAttributeMaxDynamicSharedMemorySize, GEMM_SMEM);
    cudaFuncSetAttribute((const void*)gemm_tc<true, true, false, true>,
                         cudaFuncAttributeMaxDynamicSharedMemorySize, GEMM_SMEM);

    // attention scalars + fused um pre-pass
    rs_kernel<<<II / 8, 256>>>(rated, attw, rs);
    maxexp_kernel<<<1, 1024>>>(rs, e);
    umstats_kernel<<<BB, 256>>>(um, e, umr, sB);

    // pre-round cand (A-side); round+transpose all B-side operands
    round_kernel<<<(BB * DD / 4 + 255) / 256, 256>>>(cand, candr, BB * DD / 4);
    { dim3 b(32, 8);
      transpose_tf32<<<dim3(DD / 32, II / 32), b>>>(rated, ratedT, II, DD);
      transpose_tf32<<<dim3(2 * IE_ / 32, DD / 32), b>>>(iw1, iw1t, DD, 2 * IE_);
      transpose_tf32<<<dim3(IE_ / 32, 2 * IE_ / 32), b>>>(iw2, iw2t, 2 * IE_, IE_);
      transpose_tf32<<<dim3(2 * UE_ / 32, DD / 32), b>>>(uw1, uw1t, DD, 2 * UE_);
      transpose_tf32<<<dim3(UE_ / 32, 2 * UE_ / 32), b>>>(uw2, uw2t, 2 * UE_, UE_);
      transpose_tf32<<<dim3(D1_ / 32, (IE_ + UE_) / 32), b>>>(mw1, mw1t, IE_ + UE_, D1_);
      transpose_tf32<<<dim3(D2_ / 32, D1_ / 32), b>>>(mw2, mw2t, D1_, D2_);
      transpose_tf32<<<dim3(D3_ / 32, D2_ / 32), b>>>(mw3, mw3t, D2_, D3_); }

    // uf = umr @ rated (B = ratedT), row-scaled by s in combine; splitK=4
    { dim3 g(DD / 128, BB / 128, 4);
      gemm_tc<false, false, true, false><<<g, 256, GEMM_SMEM>>>(umr, ratedT, nullptr, part, BB, DD, II, 0);
      int n4 = BB * DD / 4;
      combine_k<false, false, 4, true, true><<<(n4 + 255) / 256, 256>>>(part, nullptr, sB, uf, BB, DD, DD); }

    // ih1 = relu(candr @ iw1 + ib1)  splitK=2
    { dim3 g((2 * IE_) / 128, BB / 128, 2);
      gemm_tc<false, false, true, false><<<g, 256, GEMM_SMEM>>>(candr, iw1t, nullptr, part, BB, 2 * IE_, DD, 0);
      int n4 = BB * (2 * IE_) / 4;
      combine_k<true, true, 2, false, true><<<(n4 + 255) / 256, 256>>>(part, ib1, nullptr, ih1, BB, 2 * IE_, 2 * IE_); }

    // item_emb -> xcat[:, :512]  splitK=4
    { dim3 g(IE_ / 128, BB / 128, 4);
      gemm_tc<false, false, true, false><<<g, 256, GEMM_SMEM>>>(ih1, iw2t, nullptr, part, BB, IE_, 2 * IE_, 0);
      int n4 = BB * IE_ / 4;
      combine_k<true, true, 4, false, true><<<(n4 + 255) / 256, 256>>>(part, ib2, nullptr, xcat, BB, IE_, IE_ + UE_); }

    // uh1 = relu(uf @ uw1 + ub1)  unsplit 256 CTAs
    { dim3 g((2 * UE_) / 128, BB / 128);
      gemm_tc<true, true, false, true><<<g, 256, GEMM_SMEM>>>(uf, uw1t, ub1, uh1, BB, 2 * UE_, DD, 2 * UE_); }

    // user_emb -> xcat[:, 512:]  splitK=2
    { dim3 g(UE_ / 128, BB / 128, 2);
      gemm_tc<false, false, true, false><<<g, 256, GEMM_SMEM>>>(uh1, uw2t, nullptr, part, BB, UE_, 2 * UE_, 0);
      int n4 = BB * UE_ / 4;
      combine_k<true, true, 2, false, true><<<(n4 + 255) / 256, 256>>>(part, ub2, nullptr, xcat + IE_, BB, UE_, IE_ + UE_); }

    // x1 = relu(xcat @ mw1 + mb1)  splitK=2
    { dim3 g(D1_ / 128, BB / 128, 2);
      gemm_tc<false, false, true, false><<<g, 256, GEMM_SMEM>>>(xcat, mw1t, nullptr, part, BB, D1_, IE_ + UE_, 0);
      int n4 = BB * D1_ / 4;
      combine_k<true, true, 2, false, true><<<(n4 + 255) / 256, 256>>>(part, mb1, nullptr, x1, BB, D1_, D1_); }

    // x2 = relu(x1 @ mw2 + mb2)  splitK=4
    { dim3 g(D2_ / 128, BB / 128, 4);
      gemm_tc<false, false, true, false><<<g, 256, GEMM_SMEM>>>(x1, mw2t, nullptr, part, BB, D2_, D1_, 0);
      int n4 = BB * D2_ / 4;
      combine_k<true, true, 4, false, true><<<(n4 + 255) / 256, 256>>>(part, mb2, nullptr, x2, BB, D2_, D2_); }

    // x3 = relu(x2 @ mw3 + mb3)  splitK=8 (no round: fp32 GEMV next)
    { dim3 g(D3_ / 128, BB / 128, 8);
      gemm_tc<false, false, true, false><<<g, 256, GEMM_SMEM>>>(x2, mw3t, nullptr, part, BB, D3_, D2_, 0);
      int n4 = BB * D3_ / 4;
      combine_k<true, true, 8, false, false><<<(n4 + 255) / 256, 256>>>(part, mb3, nullptr, x3, BB, D3_, D3_); }

    final_kernel<<<BB / 8, 256>>>(x3, mw4, mb4, out);
}